// round 1
// baseline (speedup 1.0000x reference)
#include <cuda_runtime.h>
#include <math.h>

#define BATCH 2
#define SEQ   2048
#define DIM   1024
#define HEADS 16
#define HD    64
#define MROWS (BATCH*SEQ)   // 4096

// ---------------- scratch (device globals: allocation-free) ----------------
__device__ float g_q[MROWS*DIM];
__device__ float g_k[MROWS*DIM];
__device__ float g_v[MROWS*DIM];
__device__ float g_ctx[MROWS*DIM];
__device__ float g_ei[MROWS*3];     // exp(li + rel_b)
__device__ float g_ej[MROWS*3];     // exp(lj)
__device__ float g_gate[MROWS*HEADS];

// ---------------- SGEMM: C[M,N] = A[M,K] @ W[N,K]^T + bias[N] ----------------
// 128x128 tile, BK=8, 256 threads, 8x8 per thread.
__global__ __launch_bounds__(256) void sgemm_tn(
    const float* __restrict__ A, const float* __restrict__ W,
    const float* __restrict__ bias, float* __restrict__ C,
    int M, int N, int K)
{
    __shared__ float As[8][128];
    __shared__ float Ws[8][128];
    const int bm = blockIdx.y * 128;
    const int bn = blockIdx.x * 128;
    const int tid = threadIdx.x;
    const int tx = tid & 15, ty = tid >> 4;
    const int lr = tid >> 1;
    const int lc = (tid & 1) * 4;

    const float* Aptr = A + (size_t)(bm + lr) * K + lc;
    const float* Wptr = W + (size_t)(bn + lr) * K + lc;

    float acc[8][8];
#pragma unroll
    for (int i = 0; i < 8; i++)
#pragma unroll
        for (int j = 0; j < 8; j++) acc[i][j] = 0.f;

    float4 afrag = *(const float4*)(Aptr);
    float4 wfrag = *(const float4*)(Wptr);

    for (int k0 = 0; k0 < K; k0 += 8) {
        As[lc+0][lr] = afrag.x; As[lc+1][lr] = afrag.y;
        As[lc+2][lr] = afrag.z; As[lc+3][lr] = afrag.w;
        Ws[lc+0][lr] = wfrag.x; Ws[lc+1][lr] = wfrag.y;
        Ws[lc+2][lr] = wfrag.z; Ws[lc+3][lr] = wfrag.w;
        __syncthreads();
        if (k0 + 8 < K) {
            afrag = *(const float4*)(Aptr + k0 + 8);
            wfrag = *(const float4*)(Wptr + k0 + 8);
        }
#pragma unroll
        for (int kk = 0; kk < 8; kk++) {
            float4 a0 = *(const float4*)&As[kk][ty*8];
            float4 a1 = *(const float4*)&As[kk][ty*8+4];
            float4 w0 = *(const float4*)&Ws[kk][tx*8];
            float4 w1 = *(const float4*)&Ws[kk][tx*8+4];
            float av[8] = {a0.x,a0.y,a0.z,a0.w,a1.x,a1.y,a1.z,a1.w};
            float wv[8] = {w0.x,w0.y,w0.z,w0.w,w1.x,w1.y,w1.z,w1.w};
#pragma unroll
            for (int i = 0; i < 8; i++)
#pragma unroll
                for (int j = 0; j < 8; j++) acc[i][j] += av[i]*wv[j];
        }
        __syncthreads();
    }

#pragma unroll
    for (int i = 0; i < 8; i++) {
        int row = bm + ty*8 + i;
#pragma unroll
        for (int j = 0; j < 8; j += 4) {
            int col = bn + tx*8 + j;
            float4 o;
            o.x = acc[i][j+0] + bias[col+0];
            o.y = acc[i][j+1] + bias[col+1];
            o.z = acc[i][j+2] + bias[col+2];
            o.w = acc[i][j+3] + bias[col+3];
            *(float4*)(C + (size_t)row*N + col) = o;
        }
    }
}

// ---------------- small projections: ei, ej, gate ----------------
// One block (256 thr) per row of x. 22 dot products of length 1024 per row.
__global__ __launch_bounds__(256) void proj_small(
    const float* __restrict__ x,
    const float* __restrict__ relW, const float* __restrict__ relb,
    const float* __restrict__ gW,   const float* __restrict__ gb)
{
    __shared__ float xs[DIM];
    const int m = blockIdx.x;
    const float* xrow = x + (size_t)m * DIM;
    for (int i = threadIdx.x; i < DIM; i += 256) xs[i] = xrow[i];
    __syncthreads();

    const int warp = threadIdx.x >> 5;
    const int lane = threadIdx.x & 31;
    for (int o = warp; o < 22; o += 8) {
        const float* w;
        if (o < 3)       w = relW + (size_t)o * (2*DIM);
        else if (o < 6)  w = relW + (size_t)(o-3) * (2*DIM) + DIM;
        else             w = gW   + (size_t)(o-6) * DIM;
        float s = 0.f;
        for (int k = lane; k < DIM; k += 32) s += xs[k] * w[k];
#pragma unroll
        for (int off = 16; off; off >>= 1) s += __shfl_xor_sync(0xffffffffu, s, off);
        if (lane == 0) {
            if (o < 3)      g_ei[(size_t)m*3 + o]      = expf(s + relb[o]);
            else if (o < 6) g_ej[(size_t)m*3 + (o-3)]  = expf(s);
            else            g_gate[(size_t)m*HEADS + (o-6)] =
                                1.f / (1.f + expf(-(s + gb[o-6])));
        }
    }
}

// ---------------- fused flash-attention with relational bias ----------------
#define PAD 68
#define ATTN_SMEM ((64*PAD*2 + 64*64 + 64*3) * 4)   // 51968 bytes

__global__ __launch_bounds__(256) void attn_kernel(const float* __restrict__ lb)
{
    extern __shared__ float sm[];
    float* Qs  = sm;                 // [64][PAD] transposed: Qs[kk*PAD + i]
    float* KPs = Qs  + 64*PAD;       // K^T tile, later reused as P[row][j]
    float* Vs  = KPs + 64*PAD;       // [j][64]
    float* Ejs = Vs  + 64*64;        // [64][3]

    const int b  = blockIdx.z;
    const int h  = blockIdx.y;
    const int i0 = blockIdx.x * 64;
    const int tid = threadIdx.x;
    const int tx = tid & 15, ty = tid >> 4;
    const float inv_scale = 0.125f;   // 1/sqrt(HD)

    // load Q tile (transposed, pre-scaled)
    const float* qbase = g_q + ((size_t)(b*SEQ + i0))*DIM + h*HD;
    for (int t = tid; t < 64*16; t += 256) {
        int i = t >> 4, k4 = (t & 15) << 2;
        float4 q = *(const float4*)(qbase + (size_t)i*DIM + k4);
        Qs[(k4+0)*PAD + i] = q.x * inv_scale;
        Qs[(k4+1)*PAD + i] = q.y * inv_scale;
        Qs[(k4+2)*PAD + i] = q.z * inv_scale;
        Qs[(k4+3)*PAD + i] = q.w * inv_scale;
    }

    // per-thread row constants (4 rows): ei (denominator), fi = gate*ei*lb (numerator)
    float fi[4][3], eiw[4][3];
    const float lb0 = lb[h*3+0], lb1 = lb[h*3+1], lb2 = lb[h*3+2];
#pragma unroll
    for (int r = 0; r < 4; r++) {
        int gi = b*SEQ + i0 + ty*4 + r;
        float g  = g_gate[(size_t)gi*HEADS + h];
        float e0 = g_ei[(size_t)gi*3+0];
        float e1 = g_ei[(size_t)gi*3+1];
        float e2 = g_ei[(size_t)gi*3+2];
        eiw[r][0] = e0; eiw[r][1] = e1; eiw[r][2] = e2;
        fi[r][0] = g*e0*lb0; fi[r][1] = g*e1*lb1; fi[r][2] = g*e2*lb2;
    }

    float acc[4][4];
#pragma unroll
    for (int r = 0; r < 4; r++)
#pragma unroll
        for (int c = 0; c < 4; c++) acc[r][c] = 0.f;
    float mrow[4] = {-1e30f, -1e30f, -1e30f, -1e30f};
    float lrow[4] = {0.f, 0.f, 0.f, 0.f};

    const float* kbase = g_k + ((size_t)(b*SEQ))*DIM + h*HD;
    const float* vbase = g_v + ((size_t)(b*SEQ))*DIM + h*HD;

    for (int jt = 0; jt < SEQ/64; jt++) {
        const int j0 = jt * 64;
        __syncthreads();   // previous-iter P/V readers done before overwrite
        for (int t = tid; t < 64*16; t += 256) {
            int j = t >> 4, k4 = (t & 15) << 2;
            float4 kv = *(const float4*)(kbase + (size_t)(j0+j)*DIM + k4);
            KPs[(k4+0)*PAD + j] = kv.x;
            KPs[(k4+1)*PAD + j] = kv.y;
            KPs[(k4+2)*PAD + j] = kv.z;
            KPs[(k4+3)*PAD + j] = kv.w;
            float4 vv = *(const float4*)(vbase + (size_t)(j0+j)*DIM + k4);
            *(float4*)&Vs[j*64 + k4] = vv;
        }
        for (int t = tid; t < 64*3; t += 256)
            Ejs[t] = g_ej[((size_t)(b*SEQ + j0))*3 + t];
        __syncthreads();

        // ---- S = Q K^T (scaled) ----
        float s[4][4];
#pragma unroll
        for (int r = 0; r < 4; r++)
#pragma unroll
            for (int c = 0; c < 4; c++) s[r][c] = 0.f;
#pragma unroll 8
        for (int kk = 0; kk < 64; kk++) {
            float4 qf = *(const float4*)&Qs[kk*PAD + ty*4];
            float4 kf = *(const float4*)&KPs[kk*PAD + tx*4];
            float qv[4] = {qf.x, qf.y, qf.z, qf.w};
            float kvv[4] = {kf.x, kf.y, kf.z, kf.w};
#pragma unroll
            for (int r = 0; r < 4; r++)
#pragma unroll
                for (int c = 0; c < 4; c++) s[r][c] += qv[r]*kvv[c];
        }

        // ---- add gate * relational bias:  (fi . ej) / (ei . ej) ----
#pragma unroll
        for (int c = 0; c < 4; c++) {
            int j = tx*4 + c;
            float ej0 = Ejs[j*3+0], ej1 = Ejs[j*3+1], ej2 = Ejs[j*3+2];
#pragma unroll
            for (int r = 0; r < 4; r++) {
                float num = fi[r][0]*ej0 + fi[r][1]*ej1 + fi[r][2]*ej2;
                float den = eiw[r][0]*ej0 + eiw[r][1]*ej1 + eiw[r][2]*ej2;
                s[r][c] += num * __frcp_rn(den);
            }
        }

        // ---- online softmax (row reductions across the 16-lane tx group) ----
        float pnew[4][4];
#pragma unroll
        for (int r = 0; r < 4; r++) {
            float mx = fmaxf(fmaxf(s[r][0], s[r][1]), fmaxf(s[r][2], s[r][3]));
#pragma unroll
            for (int o = 1; o < 16; o <<= 1)
                mx = fmaxf(mx, __shfl_xor_sync(0xffffffffu, mx, o));
            float mn   = fmaxf(mrow[r], mx);
            float corr = __expf(mrow[r] - mn);
            float rs = 0.f;
#pragma unroll
            for (int c = 0; c < 4; c++) {
                pnew[r][c] = __expf(s[r][c] - mn);
                rs += pnew[r][c];
            }
#pragma unroll
            for (int o = 1; o < 16; o <<= 1)
                rs += __shfl_xor_sync(0xffffffffu, rs, o);
            lrow[r] = lrow[r]*corr + rs;
            mrow[r] = mn;
#pragma unroll
            for (int c = 0; c < 4; c++) acc[r][c] *= corr;
        }

        __syncthreads();   // everyone finished reading K; reuse KPs for P
#pragma unroll
        for (int r = 0; r < 4; r++)
#pragma unroll
            for (int c = 0; c < 4; c++)
                KPs[(ty*4+r)*PAD + tx*4 + c] = pnew[r][c];
        __syncthreads();

        // ---- O += P V ----
#pragma unroll 4
        for (int j = 0; j < 64; j++) {
            float4 v = *(const float4*)&Vs[j*64 + tx*4];
#pragma unroll
            for (int r = 0; r < 4; r++) {
                float p = KPs[(ty*4+r)*PAD + j];
                acc[r][0] += p*v.x; acc[r][1] += p*v.y;
                acc[r][2] += p*v.z; acc[r][3] += p*v.w;
            }
        }
    }

    // epilogue: normalize and store context
#pragma unroll
    for (int r = 0; r < 4; r++) {
        float inv = __frcp_rn(lrow[r]);
        size_t row = (size_t)(b*SEQ + i0 + ty*4 + r);
        float4 o;
        o.x = acc[r][0]*inv; o.y = acc[r][1]*inv;
        o.z = acc[r][2]*inv; o.w = acc[r][3]*inv;
        *(float4*)(g_ctx + row*DIM + h*HD + tx*4) = o;
    }
}

// ---------------- launcher ----------------
extern "C" void kernel_launch(void* const* d_in, const int* in_sizes, int n_in,
                              void* d_out, int out_size)
{
    (void)in_sizes; (void)n_in; (void)out_size;
    const float* x    = (const float*)d_in[0];
    const float* Wq   = (const float*)d_in[1];
    const float* bq   = (const float*)d_in[2];
    const float* Wk   = (const float*)d_in[3];
    const float* bk   = (const float*)d_in[4];
    const float* Wv   = (const float*)d_in[5];
    const float* bv   = (const float*)d_in[6];
    const float* Wo   = (const float*)d_in[7];
    const float* bo   = (const float*)d_in[8];
    const float* relW = (const float*)d_in[9];
    const float* relb = (const float*)d_in[10];
    const float* lb   = (const float*)d_in[11];
    const float* gW   = (const float*)d_in[12];
    const float* gb   = (const float*)d_in[13];

    float *q, *k, *v, *ctx;
    cudaGetSymbolAddress((void**)&q,   g_q);
    cudaGetSymbolAddress((void**)&k,   g_k);
    cudaGetSymbolAddress((void**)&v,   g_v);
    cudaGetSymbolAddress((void**)&ctx, g_ctx);

    cudaFuncSetAttribute(attn_kernel,
                         cudaFuncAttributeMaxDynamicSharedMemorySize, ATTN_SMEM);

    dim3 ggrid(DIM/128, MROWS/128);   // (8, 32)
    sgemm_tn<<<ggrid, 256>>>(x, Wq, bq, q, MROWS, DIM, DIM);
    sgemm_tn<<<ggrid, 256>>>(x, Wk, bk, k, MROWS, DIM, DIM);
    sgemm_tn<<<ggrid, 256>>>(x, Wv, bv, v, MROWS, DIM, DIM);
    proj_small<<<MROWS, 256>>>(x, relW, relb, gW, gb);

    attn_kernel<<<dim3(SEQ/64, HEADS, BATCH), 256, ATTN_SMEM>>>(lb);

    sgemm_tn<<<ggrid, 256>>>(ctx, Wo, bo, (float*)d_out, MROWS, DIM, DIM);
}

// round 2
// speedup vs baseline: 1.2328x; 1.2328x over previous
#include <cuda_runtime.h>
#include <cuda_bf16.h>
#include <math.h>

#define BATCH 2
#define SEQ   2048
#define DIM   1024
#define HEADS 16
#define HD    64
#define MROWS (BATCH*SEQ)   // 4096

// ---------------- scratch (device globals: allocation-free) ----------------
__device__ float g_q[MROWS*DIM];
__device__ float g_k[MROWS*DIM];
__device__ float g_v[MROWS*DIM];
__device__ float g_ctx[MROWS*DIM];
__device__ float g_ei[MROWS*3];     // exp(li + rel_b)
__device__ float g_ej[MROWS*3];     // exp(lj)
__device__ float g_gate[MROWS*HEADS];

// ============================================================================
// Tensor-core GEMM: C[M,N] = A[M,K] @ W[N,K]^T + bias[N]
// bf16 split (hi/lo) x 3 MMA passes => fp32-level accuracy on HMMA pipe.
// 128x128 block tile, BK=32, 256 threads (8 warps, 2x4 warp grid).
// ============================================================================

__device__ __forceinline__ unsigned pack_bf16(__nv_bfloat16 a, __nv_bfloat16 b) {
    return (unsigned)__bfloat16_as_ushort(a) | ((unsigned)__bfloat16_as_ushort(b) << 16);
}

#define MMA_BF16(c, a, b) \
    asm volatile("mma.sync.aligned.m16n8k16.row.col.f32.bf16.bf16.f32 " \
                 "{%0,%1,%2,%3}, {%4,%5,%6,%7}, {%8,%9}, {%0,%1,%2,%3};" \
                 : "+f"(c[0]), "+f"(c[1]), "+f"(c[2]), "+f"(c[3]) \
                 : "r"(a[0]), "r"(a[1]), "r"(a[2]), "r"(a[3]), "r"(b[0]), "r"(b[1]))

#define SSTR 40   // smem row stride in bf16 elems (40*2=80B: 16B-mult, conflict-free)

__global__ __launch_bounds__(256) void sgemm_bf16x3(
    const float* __restrict__ A, const float* __restrict__ W,
    const float* __restrict__ bias, float* __restrict__ C,
    int M, int N, int K)
{
    __shared__ __nv_bfloat16 sAh[128][SSTR];
    __shared__ __nv_bfloat16 sAl[128][SSTR];
    __shared__ __nv_bfloat16 sBh[128][SSTR];
    __shared__ __nv_bfloat16 sBl[128][SSTR];

    const int bm = blockIdx.y * 128;
    const int bn = blockIdx.x * 128;
    const int tid = threadIdx.x;
    const int lane = tid & 31;
    const int w = tid >> 5;
    const int wm = (w >> 2) * 64;   // warp row offset within tile
    const int wn = (w & 3) * 32;    // warp col offset within tile
    const int g  = lane >> 2;       // groupID
    const int tc = (lane & 3) * 2;  // thread col pair

    // loader mapping: each thread owns 4 float4's of A and 4 of W per BK slab
    const int tr  = tid >> 3;        // base row 0..31 (+32*i)
    const int tc4 = (tid & 7) * 4;   // col within 32-wide slab

    const float* Aptr = A + (size_t)(bm + tr) * K + tc4;
    const float* Wptr = W + (size_t)(bn + tr) * K + tc4;

    float acc[4][4][4];
#pragma unroll
    for (int mi = 0; mi < 4; mi++)
#pragma unroll
        for (int ni = 0; ni < 4; ni++)
#pragma unroll
            for (int c = 0; c < 4; c++) acc[mi][ni][c] = 0.f;

    float4 ra[4], rb[4];
#pragma unroll
    for (int i = 0; i < 4; i++) {
        ra[i] = *(const float4*)(Aptr + (size_t)(i * 32) * K);
        rb[i] = *(const float4*)(Wptr + (size_t)(i * 32) * K);
    }

    for (int k0 = 0; k0 < K; k0 += 32) {
        // ---- convert + store to smem (hi/lo split) ----
#pragma unroll
        for (int i = 0; i < 4; i++) {
            int row = tr + i * 32;
            float vv[4] = {ra[i].x, ra[i].y, ra[i].z, ra[i].w};
            __nv_bfloat16 h[4], l[4];
#pragma unroll
            for (int j = 0; j < 4; j++) {
                h[j] = __float2bfloat16_rn(vv[j]);
                l[j] = __float2bfloat16_rn(vv[j] - __bfloat162float(h[j]));
            }
            *(uint2*)&sAh[row][tc4] = make_uint2(pack_bf16(h[0], h[1]), pack_bf16(h[2], h[3]));
            *(uint2*)&sAl[row][tc4] = make_uint2(pack_bf16(l[0], l[1]), pack_bf16(l[2], l[3]));

            float wv[4] = {rb[i].x, rb[i].y, rb[i].z, rb[i].w};
#pragma unroll
            for (int j = 0; j < 4; j++) {
                h[j] = __float2bfloat16_rn(wv[j]);
                l[j] = __float2bfloat16_rn(wv[j] - __bfloat162float(h[j]));
            }
            *(uint2*)&sBh[row][tc4] = make_uint2(pack_bf16(h[0], h[1]), pack_bf16(h[2], h[3]));
            *(uint2*)&sBl[row][tc4] = make_uint2(pack_bf16(l[0], l[1]), pack_bf16(l[2], l[3]));
        }
        __syncthreads();

        // ---- prefetch next slab from gmem ----
        if (k0 + 32 < K) {
#pragma unroll
            for (int i = 0; i < 4; i++) {
                ra[i] = *(const float4*)(Aptr + k0 + 32 + (size_t)(i * 32) * K);
                rb[i] = *(const float4*)(Wptr + k0 + 32 + (size_t)(i * 32) * K);
            }
        }

        // ---- compute: 2 k-steps of 16 ----
#pragma unroll
        for (int ks = 0; ks < 32; ks += 16) {
            unsigned ah[4][4], al[4][4], bh[4][2], bl[4][2];
#pragma unroll
            for (int mi = 0; mi < 4; mi++) {
                int r = wm + mi * 16;
                ah[mi][0] = *(const unsigned*)&sAh[r + g    ][ks + tc    ];
                ah[mi][1] = *(const unsigned*)&sAh[r + g + 8][ks + tc    ];
                ah[mi][2] = *(const unsigned*)&sAh[r + g    ][ks + tc + 8];
                ah[mi][3] = *(const unsigned*)&sAh[r + g + 8][ks + tc + 8];
                al[mi][0] = *(const unsigned*)&sAl[r + g    ][ks + tc    ];
                al[mi][1] = *(const unsigned*)&sAl[r + g + 8][ks + tc    ];
                al[mi][2] = *(const unsigned*)&sAl[r + g    ][ks + tc + 8];
                al[mi][3] = *(const unsigned*)&sAl[r + g + 8][ks + tc + 8];
            }
#pragma unroll
            for (int ni = 0; ni < 4; ni++) {
                int n = wn + ni * 8 + g;
                bh[ni][0] = *(const unsigned*)&sBh[n][ks + tc    ];
                bh[ni][1] = *(const unsigned*)&sBh[n][ks + tc + 8];
                bl[ni][0] = *(const unsigned*)&sBl[n][ks + tc    ];
                bl[ni][1] = *(const unsigned*)&sBl[n][ks + tc + 8];
            }
#pragma unroll
            for (int mi = 0; mi < 4; mi++)
#pragma unroll
                for (int ni = 0; ni < 4; ni++) {
                    MMA_BF16(acc[mi][ni], ah[mi], bh[ni]);
                    MMA_BF16(acc[mi][ni], al[mi], bh[ni]);
                    MMA_BF16(acc[mi][ni], ah[mi], bl[ni]);
                }
        }
        __syncthreads();
    }

    // ---- epilogue: bias + store ----
#pragma unroll
    for (int mi = 0; mi < 4; mi++) {
        int r0 = bm + wm + mi * 16 + g;
#pragma unroll
        for (int ni = 0; ni < 4; ni++) {
            int c0 = bn + wn + ni * 8 + tc;
            float2 bb = *(const float2*)&bias[c0];
            float2 o0 = make_float2(acc[mi][ni][0] + bb.x, acc[mi][ni][1] + bb.y);
            float2 o1 = make_float2(acc[mi][ni][2] + bb.x, acc[mi][ni][3] + bb.y);
            *(float2*)(C + (size_t)r0 * N + c0)       = o0;
            *(float2*)(C + (size_t)(r0 + 8) * N + c0) = o1;
        }
    }
}

// ---------------- small projections: ei, ej, gate ----------------
__global__ __launch_bounds__(256) void proj_small(
    const float* __restrict__ x,
    const float* __restrict__ relW, const float* __restrict__ relb,
    const float* __restrict__ gW,   const float* __restrict__ gb)
{
    __shared__ float xs[DIM];
    const int m = blockIdx.x;
    const float* xrow = x + (size_t)m * DIM;
    for (int i = threadIdx.x; i < DIM; i += 256) xs[i] = xrow[i];
    __syncthreads();

    const int warp = threadIdx.x >> 5;
    const int lane = threadIdx.x & 31;
    for (int o = warp; o < 22; o += 8) {
        const float* w;
        if (o < 3)       w = relW + (size_t)o * (2*DIM);
        else if (o < 6)  w = relW + (size_t)(o-3) * (2*DIM) + DIM;
        else             w = gW   + (size_t)(o-6) * DIM;
        float s = 0.f;
        for (int k = lane; k < DIM; k += 32) s += xs[k] * w[k];
#pragma unroll
        for (int off = 16; off; off >>= 1) s += __shfl_xor_sync(0xffffffffu, s, off);
        if (lane == 0) {
            if (o < 3)      g_ei[(size_t)m*3 + o]      = expf(s + relb[o]);
            else if (o < 6) g_ej[(size_t)m*3 + (o-3)]  = expf(s);
            else            g_gate[(size_t)m*HEADS + (o-6)] =
                                1.f / (1.f + expf(-(s + gb[o-6])));
        }
    }
}

// ---------------- fused flash-attention with relational bias ----------------
#define PAD 68
#define ATTN_SMEM ((64*PAD*2 + 64*64 + 64*3) * 4)   // 51968 bytes

__global__ __launch_bounds__(256) void attn_kernel(const float* __restrict__ lb)
{
    extern __shared__ float sm[];
    float* Qs  = sm;                 // [64][PAD] transposed: Qs[kk*PAD + i]
    float* KPs = Qs  + 64*PAD;       // K^T tile, later reused as P[row][j]
    float* Vs  = KPs + 64*PAD;       // [j][64]
    float* Ejs = Vs  + 64*64;        // [64][3]

    const int b  = blockIdx.z;
    const int h  = blockIdx.y;
    const int i0 = blockIdx.x * 64;
    const int tid = threadIdx.x;
    const int tx = tid & 15, ty = tid >> 4;
    const float inv_scale = 0.125f;   // 1/sqrt(HD)

    const float* qbase = g_q + ((size_t)(b*SEQ + i0))*DIM + h*HD;
    for (int t = tid; t < 64*16; t += 256) {
        int i = t >> 4, k4 = (t & 15) << 2;
        float4 q = *(const float4*)(qbase + (size_t)i*DIM + k4);
        Qs[(k4+0)*PAD + i] = q.x * inv_scale;
        Qs[(k4+1)*PAD + i] = q.y * inv_scale;
        Qs[(k4+2)*PAD + i] = q.z * inv_scale;
        Qs[(k4+3)*PAD + i] = q.w * inv_scale;
    }

    float fi[4][3], eiw[4][3];
    const float lb0 = lb[h*3+0], lb1 = lb[h*3+1], lb2 = lb[h*3+2];
#pragma unroll
    for (int r = 0; r < 4; r++) {
        int gi = b*SEQ + i0 + ty*4 + r;
        float gg = g_gate[(size_t)gi*HEADS + h];
        float e0 = g_ei[(size_t)gi*3+0];
        float e1 = g_ei[(size_t)gi*3+1];
        float e2 = g_ei[(size_t)gi*3+2];
        eiw[r][0] = e0; eiw[r][1] = e1; eiw[r][2] = e2;
        fi[r][0] = gg*e0*lb0; fi[r][1] = gg*e1*lb1; fi[r][2] = gg*e2*lb2;
    }

    float acc[4][4];
#pragma unroll
    for (int r = 0; r < 4; r++)
#pragma unroll
        for (int c = 0; c < 4; c++) acc[r][c] = 0.f;
    float mrow[4] = {-1e30f, -1e30f, -1e30f, -1e30f};
    float lrow[4] = {0.f, 0.f, 0.f, 0.f};

    const float* kbase = g_k + ((size_t)(b*SEQ))*DIM + h*HD;
    const float* vbase = g_v + ((size_t)(b*SEQ))*DIM + h*HD;

    for (int jt = 0; jt < SEQ/64; jt++) {
        const int j0 = jt * 64;
        __syncthreads();
        for (int t = tid; t < 64*16; t += 256) {
            int j = t >> 4, k4 = (t & 15) << 2;
            float4 kv = *(const float4*)(kbase + (size_t)(j0+j)*DIM + k4);
            KPs[(k4+0)*PAD + j] = kv.x;
            KPs[(k4+1)*PAD + j] = kv.y;
            KPs[(k4+2)*PAD + j] = kv.z;
            KPs[(k4+3)*PAD + j] = kv.w;
            float4 vv = *(const float4*)(vbase + (size_t)(j0+j)*DIM + k4);
            *(float4*)&Vs[j*64 + k4] = vv;
        }
        for (int t = tid; t < 64*3; t += 256)
            Ejs[t] = g_ej[((size_t)(b*SEQ + j0))*3 + t];
        __syncthreads();

        float s[4][4];
#pragma unroll
        for (int r = 0; r < 4; r++)
#pragma unroll
            for (int c = 0; c < 4; c++) s[r][c] = 0.f;
#pragma unroll 8
        for (int kk = 0; kk < 64; kk++) {
            float4 qf = *(const float4*)&Qs[kk*PAD + ty*4];
            float4 kf = *(const float4*)&KPs[kk*PAD + tx*4];
            float qv[4] = {qf.x, qf.y, qf.z, qf.w};
            float kvv[4] = {kf.x, kf.y, kf.z, kf.w};
#pragma unroll
            for (int r = 0; r < 4; r++)
#pragma unroll
                for (int c = 0; c < 4; c++) s[r][c] += qv[r]*kvv[c];
        }

#pragma unroll
        for (int c = 0; c < 4; c++) {
            int j = tx*4 + c;
            float ej0 = Ejs[j*3+0], ej1 = Ejs[j*3+1], ej2 = Ejs[j*3+2];
#pragma unroll
            for (int r = 0; r < 4; r++) {
                float num = fi[r][0]*ej0 + fi[r][1]*ej1 + fi[r][2]*ej2;
                float den = eiw[r][0]*ej0 + eiw[r][1]*ej1 + eiw[r][2]*ej2;
                s[r][c] += num * __frcp_rn(den);
            }
        }

        float pnew[4][4];
#pragma unroll
        for (int r = 0; r < 4; r++) {
            float mx = fmaxf(fmaxf(s[r][0], s[r][1]), fmaxf(s[r][2], s[r][3]));
#pragma unroll
            for (int o = 1; o < 16; o <<= 1)
                mx = fmaxf(mx, __shfl_xor_sync(0xffffffffu, mx, o));
            float mn   = fmaxf(mrow[r], mx);
            float corr = __expf(mrow[r] - mn);
            float rs = 0.f;
#pragma unroll
            for (int c = 0; c < 4; c++) {
                pnew[r][c] = __expf(s[r][c] - mn);
                rs += pnew[r][c];
            }
#pragma unroll
            for (int o = 1; o < 16; o <<= 1)
                rs += __shfl_xor_sync(0xffffffffu, rs, o);
            lrow[r] = lrow[r]*corr + rs;
            mrow[r] = mn;
#pragma unroll
            for (int c = 0; c < 4; c++) acc[r][c] *= corr;
        }

        __syncthreads();
#pragma unroll
        for (int r = 0; r < 4; r++)
#pragma unroll
            for (int c = 0; c < 4; c++)
                KPs[(ty*4+r)*PAD + tx*4 + c] = pnew[r][c];
        __syncthreads();

#pragma unroll 4
        for (int j = 0; j < 64; j++) {
            float4 v = *(const float4*)&Vs[j*64 + tx*4];
#pragma unroll
            for (int r = 0; r < 4; r++) {
                float p = KPs[(ty*4+r)*PAD + j];
                acc[r][0] += p*v.x; acc[r][1] += p*v.y;
                acc[r][2] += p*v.z; acc[r][3] += p*v.w;
            }
        }
    }

#pragma unroll
    for (int r = 0; r < 4; r++) {
        float inv = __frcp_rn(lrow[r]);
        size_t row = (size_t)(b*SEQ + i0 + ty*4 + r);
        float4 o;
        o.x = acc[r][0]*inv; o.y = acc[r][1]*inv;
        o.z = acc[r][2]*inv; o.w = acc[r][3]*inv;
        *(float4*)(g_ctx + row*DIM + h*HD + tx*4) = o;
    }
}

// ---------------- launcher ----------------
extern "C" void kernel_launch(void* const* d_in, const int* in_sizes, int n_in,
                              void* d_out, int out_size)
{
    (void)in_sizes; (void)n_in; (void)out_size;
    const float* x    = (const float*)d_in[0];
    const float* Wq   = (const float*)d_in[1];
    const float* bq   = (const float*)d_in[2];
    const float* Wk   = (const float*)d_in[3];
    const float* bk   = (const float*)d_in[4];
    const float* Wv   = (const float*)d_in[5];
    const float* bv   = (const float*)d_in[6];
    const float* Wo   = (const float*)d_in[7];
    const float* bo   = (const float*)d_in[8];
    const float* relW = (const float*)d_in[9];
    const float* relb = (const float*)d_in[10];
    const float* lb   = (const float*)d_in[11];
    const float* gW   = (const float*)d_in[12];
    const float* gb   = (const float*)d_in[13];

    float *q, *k, *v, *ctx;
    cudaGetSymbolAddress((void**)&q,   g_q);
    cudaGetSymbolAddress((void**)&k,   g_k);
    cudaGetSymbolAddress((void**)&v,   g_v);
    cudaGetSymbolAddress((void**)&ctx, g_ctx);

    cudaFuncSetAttribute(attn_kernel,
                         cudaFuncAttributeMaxDynamicSharedMemorySize, ATTN_SMEM);

    dim3 ggrid(DIM/128, MROWS/128);   // (8, 32)
    sgemm_bf16x3<<<ggrid, 256>>>(x, Wq, bq, q, MROWS, DIM, DIM);
    sgemm_bf16x3<<<ggrid, 256>>>(x, Wk, bk, k, MROWS, DIM, DIM);
    sgemm_bf16x3<<<ggrid, 256>>>(x, Wv, bv, v, MROWS, DIM, DIM);
    proj_small<<<MROWS, 256>>>(x, relW, relb, gW, gb);

    attn_kernel<<<dim3(SEQ/64, HEADS, BATCH), 256, ATTN_SMEM>>>(lb);

    sgemm_bf16x3<<<ggrid, 256>>>(ctx, Wo, bo, (float*)d_out, MROWS, DIM, DIM);
}

// round 6
// speedup vs baseline: 1.6831x; 1.3652x over previous
#include <cuda_runtime.h>
#include <cuda_bf16.h>
#include <math.h>

#define BATCH 2
#define SEQ   2048
#define DIM   1024
#define HEADS 16
#define HD    64
#define MROWS (BATCH*SEQ)

// ---------------- scratch (device globals: allocation-free) ----------------
__device__ float g_q[MROWS*DIM];
__device__ float g_k[MROWS*DIM];
__device__ float g_v[MROWS*DIM];
__device__ float g_ctx[MROWS*DIM];
__device__ float g_ei[MROWS*3];
__device__ float g_ej[MROWS*3];
__device__ float g_gate[MROWS*HEADS];

// ---------------- helpers (R2-proven set only) ----------------
__device__ __forceinline__ unsigned pack_bf16(__nv_bfloat16 a, __nv_bfloat16 b) {
    return (unsigned)__bfloat16_as_ushort(a) | ((unsigned)__bfloat16_as_ushort(b) << 16);
}

#define MMA_BF16(c, a, b) \
    asm volatile("mma.sync.aligned.m16n8k16.row.col.f32.bf16.bf16.f32 " \
                 "{%0,%1,%2,%3}, {%4,%5,%6,%7}, {%8,%9}, {%0,%1,%2,%3};" \
                 : "+f"(c[0]), "+f"(c[1]), "+f"(c[2]), "+f"(c[3]) \
                 : "r"(a[0]), "r"(a[1]), "r"(a[2]), "r"(a[3]), "r"(b[0]), "r"(b[1]))

// ============================================================================
// GEMM: C = A @ W^T + bias  (exact R2 kernel, compiled+passed before)
// ============================================================================
#define SSTR 40

__global__ __launch_bounds__(256) void sgemm_bf16x3(
    const float* __restrict__ A, const float* __restrict__ W,
    const float* __restrict__ bias, float* __restrict__ C,
    int M, int N, int K)
{
    __shared__ __nv_bfloat16 sAh[128][SSTR];
    __shared__ __nv_bfloat16 sAl[128][SSTR];
    __shared__ __nv_bfloat16 sBh[128][SSTR];
    __shared__ __nv_bfloat16 sBl[128][SSTR];

    const int bm = blockIdx.y * 128;
    const int bn = blockIdx.x * 128;
    const int tid = threadIdx.x;
    const int lane = tid & 31;
    const int w = tid >> 5;
    const int wm = (w >> 2) * 64;
    const int wn = (w & 3) * 32;
    const int g  = lane >> 2;
    const int tc = (lane & 3) * 2;
    const int tr  = tid >> 3;
    const int tc4 = (tid & 7) * 4;

    const float* Aptr = A + (size_t)(bm + tr) * K + tc4;
    const float* Wptr = W + (size_t)(bn + tr) * K + tc4;

    float acc[4][4][4];
#pragma unroll
    for (int mi = 0; mi < 4; mi++)
#pragma unroll
        for (int ni = 0; ni < 4; ni++)
#pragma unroll
            for (int c = 0; c < 4; c++) acc[mi][ni][c] = 0.f;

    float4 ra[4], rb[4];
#pragma unroll
    for (int i = 0; i < 4; i++) {
        ra[i] = *(const float4*)(Aptr + (size_t)(i * 32) * K);
        rb[i] = *(const float4*)(Wptr + (size_t)(i * 32) * K);
    }

    for (int k0 = 0; k0 < K; k0 += 32) {
#pragma unroll
        for (int i = 0; i < 4; i++) {
            int row = tr + i * 32;
            float vv[4] = {ra[i].x, ra[i].y, ra[i].z, ra[i].w};
            __nv_bfloat16 h[4], l[4];
#pragma unroll
            for (int j = 0; j < 4; j++) {
                h[j] = __float2bfloat16_rn(vv[j]);
                l[j] = __float2bfloat16_rn(vv[j] - __bfloat162float(h[j]));
            }
            *(uint2*)&sAh[row][tc4] = make_uint2(pack_bf16(h[0], h[1]), pack_bf16(h[2], h[3]));
            *(uint2*)&sAl[row][tc4] = make_uint2(pack_bf16(l[0], l[1]), pack_bf16(l[2], l[3]));

            float wv[4] = {rb[i].x, rb[i].y, rb[i].z, rb[i].w};
#pragma unroll
            for (int j = 0; j < 4; j++) {
                h[j] = __float2bfloat16_rn(wv[j]);
                l[j] = __float2bfloat16_rn(wv[j] - __bfloat162float(h[j]));
            }
            *(uint2*)&sBh[row][tc4] = make_uint2(pack_bf16(h[0], h[1]), pack_bf16(h[2], h[3]));
            *(uint2*)&sBl[row][tc4] = make_uint2(pack_bf16(l[0], l[1]), pack_bf16(l[2], l[3]));
        }
        __syncthreads();

        if (k0 + 32 < K) {
#pragma unroll
            for (int i = 0; i < 4; i++) {
                ra[i] = *(const float4*)(Aptr + k0 + 32 + (size_t)(i * 32) * K);
                rb[i] = *(const float4*)(Wptr + k0 + 32 + (size_t)(i * 32) * K);
            }
        }

#pragma unroll
        for (int ks = 0; ks < 32; ks += 16) {
            unsigned ah[4][4], al[4][4], bh[4][2], bl[4][2];
#pragma unroll
            for (int mi = 0; mi < 4; mi++) {
                int r = wm + mi * 16;
                ah[mi][0] = *(const unsigned*)&sAh[r + g    ][ks + tc    ];
                ah[mi][1] = *(const unsigned*)&sAh[r + g + 8][ks + tc    ];
                ah[mi][2] = *(const unsigned*)&sAh[r + g    ][ks + tc + 8];
                ah[mi][3] = *(const unsigned*)&sAh[r + g + 8][ks + tc + 8];
                al[mi][0] = *(const unsigned*)&sAl[r + g    ][ks + tc    ];
                al[mi][1] = *(const unsigned*)&sAl[r + g + 8][ks + tc    ];
                al[mi][2] = *(const unsigned*)&sAl[r + g    ][ks + tc + 8];
                al[mi][3] = *(const unsigned*)&sAl[r + g + 8][ks + tc + 8];
            }
#pragma unroll
            for (int ni = 0; ni < 4; ni++) {
                int n = wn + ni * 8 + g;
                bh[ni][0] = *(const unsigned*)&sBh[n][ks + tc    ];
                bh[ni][1] = *(const unsigned*)&sBh[n][ks + tc + 8];
                bl[ni][0] = *(const unsigned*)&sBl[n][ks + tc    ];
                bl[ni][1] = *(const unsigned*)&sBl[n][ks + tc + 8];
            }
#pragma unroll
            for (int mi = 0; mi < 4; mi++)
#pragma unroll
                for (int ni = 0; ni < 4; ni++) {
                    MMA_BF16(acc[mi][ni], ah[mi], bh[ni]);
                    MMA_BF16(acc[mi][ni], al[mi], bh[ni]);
                    MMA_BF16(acc[mi][ni], ah[mi], bl[ni]);
                }
        }
        __syncthreads();
    }

#pragma unroll
    for (int mi = 0; mi < 4; mi++) {
        int r0 = bm + wm + mi * 16 + g;
#pragma unroll
        for (int ni = 0; ni < 4; ni++) {
            int c0 = bn + wn + ni * 8 + tc;
            float2 bb = *(const float2*)&bias[c0];
            float2 o0 = make_float2(acc[mi][ni][0] + bb.x, acc[mi][ni][1] + bb.y);
            float2 o1 = make_float2(acc[mi][ni][2] + bb.x, acc[mi][ni][3] + bb.y);
            *(float2*)(C + (size_t)r0 * N + c0)       = o0;
            *(float2*)(C + (size_t)(r0 + 8) * N + c0) = o1;
        }
    }
}

// ---------------- small projections (R2-proven) ----------------
__global__ __launch_bounds__(256) void proj_small(
    const float* __restrict__ x,
    const float* __restrict__ relW, const float* __restrict__ relb,
    const float* __restrict__ gW,   const float* __restrict__ gb)
{
    __shared__ float xs[DIM];
    const int m = blockIdx.x;
    const float* xrow = x + (size_t)m * DIM;
    for (int i = threadIdx.x; i < DIM; i += 256) xs[i] = xrow[i];
    __syncthreads();

    const int warp = threadIdx.x >> 5;
    const int lane = threadIdx.x & 31;
    for (int o = warp; o < 22; o += 8) {
        const float* wp;
        if (o < 3)       wp = relW + (size_t)o * (2*DIM);
        else if (o < 6)  wp = relW + (size_t)(o-3) * (2*DIM) + DIM;
        else             wp = gW   + (size_t)(o-6) * DIM;
        float s = 0.f;
        for (int k = lane; k < DIM; k += 32) s += xs[k] * wp[k];
#pragma unroll
        for (int off = 16; off; off >>= 1) s += __shfl_xor_sync(0xffffffffu, s, off);
        if (lane == 0) {
            if (o < 3)      g_ei[(size_t)m*3 + o]      = expf(s + relb[o]);
            else if (o < 6) g_ej[(size_t)m*3 + (o-3)]  = expf(s);
            else            g_gate[(size_t)m*HEADS + (o-6)] =
                                1.f / (1.f + expf(-(s + gb[o-6])));
        }
    }
}

// ============================================================================
// Fused flash-attention on tensor cores, R2-idiom fragments (no ldmatrix).
// Tiles: Q/K/P row-major k-contiguous (stride 72), V transposed (stride 66).
// ============================================================================
#define BSTR 72
#define VSTR 66
#define PADS 68
#define ATTN_SMEM ((6*64*BSTR + 2*64*VSTR)*2 + 64*PADS*4 + 192*4 + 64*4)

__global__ __launch_bounds__(256) void attn_mma(const float* __restrict__ lb)
{
    extern __shared__ __nv_bfloat16 smb[];
    __nv_bfloat16* Qh  = smb;
    __nv_bfloat16* Ql  = Qh  + 64*BSTR;
    __nv_bfloat16* Kh  = Ql  + 64*BSTR;
    __nv_bfloat16* Kl  = Kh  + 64*BSTR;
    __nv_bfloat16* Ph  = Kl  + 64*BSTR;
    __nv_bfloat16* Pl  = Ph  + 64*BSTR;
    __nv_bfloat16* Vth = Pl  + 64*BSTR;
    __nv_bfloat16* Vtl = Vth + 64*VSTR;
    float* Ss      = (float*)(Vtl + 64*VSTR);
    float* Ejs     = Ss + 64*PADS;
    float* corrbuf = Ejs + 192;

    const int bb = blockIdx.z;
    const int hh = blockIdx.y;
    const int i0 = blockIdx.x * 64;
    const int tid  = threadIdx.x;
    const int lane = tid & 31;
    const int w    = tid >> 5;
    const int wm = (w >> 1) * 16;
    const int wn = (w & 1) * 32;
    const int g  = lane >> 2;
    const int tc = (lane & 3) * 2;
    const int tx = tid & 15;
    const int ty = tid >> 4;

    // ---- Q tile fill: scale 1/8, hi/lo split, row-major [i][d] ----
    const float* qbase = g_q + ((size_t)(bb*SEQ + i0))*DIM + hh*HD;
    for (int t = tid; t < 64*16; t += 256) {
        int i = t >> 4;
        int k4 = (t & 15) << 2;
        float4 qv = *(const float4*)(qbase + (size_t)i*DIM + k4);
        float vv[4] = {qv.x*0.125f, qv.y*0.125f, qv.z*0.125f, qv.w*0.125f};
        __nv_bfloat16 h[4], l[4];
#pragma unroll
        for (int j = 0; j < 4; j++) {
            h[j] = __float2bfloat16_rn(vv[j]);
            l[j] = __float2bfloat16_rn(vv[j] - __bfloat162float(h[j]));
        }
        *(uint2*)&Qh[i*BSTR + k4] = make_uint2(pack_bf16(h[0], h[1]), pack_bf16(h[2], h[3]));
        *(uint2*)&Ql[i*BSTR + k4] = make_uint2(pack_bf16(l[0], l[1]), pack_bf16(l[2], l[3]));
    }

    // ---- per-row relational constants (softmax layout: rows ty*4+r) ----
    float fi[4][3], eiw[4][3];
    const float lb0 = lb[hh*3+0];
    const float lb1 = lb[hh*3+1];
    const float lb2 = lb[hh*3+2];
#pragma unroll
    for (int r = 0; r < 4; r++) {
        int gi = bb*SEQ + i0 + ty*4 + r;
        float gg = g_gate[(size_t)gi*HEADS + hh];
        float e0 = g_ei[(size_t)gi*3+0];
        float e1 = g_ei[(size_t)gi*3+1];
        float e2 = g_ei[(size_t)gi*3+2];
        eiw[r][0] = e0; eiw[r][1] = e1; eiw[r][2] = e2;
        fi[r][0] = gg*e0*lb0; fi[r][1] = gg*e1*lb1; fi[r][2] = gg*e2*lb2;
    }
    __syncthreads();

    // ---- Q a-fragments (j-invariant), plain 32-bit loads ----
    unsigned qah[4][4], qal[4][4];
#pragma unroll
    for (int ks = 0; ks < 4; ks++) {
        int k0 = ks * 16;
        qah[ks][0] = *(const unsigned*)&Qh[(wm + g    )*BSTR + k0 + tc    ];
        qah[ks][1] = *(const unsigned*)&Qh[(wm + g + 8)*BSTR + k0 + tc    ];
        qah[ks][2] = *(const unsigned*)&Qh[(wm + g    )*BSTR + k0 + tc + 8];
        qah[ks][3] = *(const unsigned*)&Qh[(wm + g + 8)*BSTR + k0 + tc + 8];
        qal[ks][0] = *(const unsigned*)&Ql[(wm + g    )*BSTR + k0 + tc    ];
        qal[ks][1] = *(const unsigned*)&Ql[(wm + g + 8)*BSTR + k0 + tc    ];
        qal[ks][2] = *(const unsigned*)&Ql[(wm + g    )*BSTR + k0 + tc + 8];
        qal[ks][3] = *(const unsigned*)&Ql[(wm + g + 8)*BSTR + k0 + tc + 8];
    }

    float acc[4][4];
#pragma unroll
    for (int ni = 0; ni < 4; ni++)
#pragma unroll
        for (int c = 0; c < 4; c++) acc[ni][c] = 0.f;
    float mrow[4] = {-1e30f, -1e30f, -1e30f, -1e30f};
    float lrow[4] = {0.f, 0.f, 0.f, 0.f};

    const float* kbase = g_k + ((size_t)(bb*SEQ))*DIM + hh*HD;
    const float* vbase = g_v + ((size_t)(bb*SEQ))*DIM + hh*HD;

    for (int jt = 0; jt < SEQ/64; jt++) {
        const int j0 = jt * 64;
        __syncthreads();   // previous-iter PV readers done before overwrite

        // ---- K fill (row-major [j][d]) + V fill (transposed [d][j]) ----
        for (int t = tid; t < 64*16; t += 256) {
            int j = t >> 4;
            int k4 = (t & 15) << 2;
            float4 kv = *(const float4*)(kbase + (size_t)(j0+j)*DIM + k4);
            float vv[4] = {kv.x, kv.y, kv.z, kv.w};
            __nv_bfloat16 h[4], l[4];
#pragma unroll
            for (int jj = 0; jj < 4; jj++) {
                h[jj] = __float2bfloat16_rn(vv[jj]);
                l[jj] = __float2bfloat16_rn(vv[jj] - __bfloat162float(h[jj]));
            }
            *(uint2*)&Kh[j*BSTR + k4] = make_uint2(pack_bf16(h[0], h[1]), pack_bf16(h[2], h[3]));
            *(uint2*)&Kl[j*BSTR + k4] = make_uint2(pack_bf16(l[0], l[1]), pack_bf16(l[2], l[3]));

            float4 vvec = *(const float4*)(vbase + (size_t)(j0+j)*DIM + k4);
            float vw[4] = {vvec.x, vvec.y, vvec.z, vvec.w};
#pragma unroll
            for (int jj = 0; jj < 4; jj++) {
                __nv_bfloat16 vh = __float2bfloat16_rn(vw[jj]);
                __nv_bfloat16 vl = __float2bfloat16_rn(vw[jj] - __bfloat162float(vh));
                Vth[(k4 + jj)*VSTR + j] = vh;
                Vtl[(k4 + jj)*VSTR + j] = vl;
            }
        }
        for (int t = tid; t < 64*3; t += 256) {
            Ejs[t] = g_ej[((size_t)(bb*SEQ + j0))*3 + t];
        }
        __syncthreads();

        // ---- S = Q K^T (3-pass split MMA, K b-frags like sgemm W) ----
        float sc[4][4];
#pragma unroll
        for (int ni = 0; ni < 4; ni++)
#pragma unroll
            for (int c = 0; c < 4; c++) sc[ni][c] = 0.f;
#pragma unroll
        for (int ks = 0; ks < 4; ks++) {
            int k0 = ks * 16;
            unsigned bh[4][2], bl[4][2];
#pragma unroll
            for (int ni = 0; ni < 4; ni++) {
                int n = wn + ni * 8 + g;
                bh[ni][0] = *(const unsigned*)&Kh[n*BSTR + k0 + tc    ];
                bh[ni][1] = *(const unsigned*)&Kh[n*BSTR + k0 + tc + 8];
                bl[ni][0] = *(const unsigned*)&Kl[n*BSTR + k0 + tc    ];
                bl[ni][1] = *(const unsigned*)&Kl[n*BSTR + k0 + tc + 8];
            }
#pragma unroll
            for (int ni = 0; ni < 4; ni++) {
                MMA_BF16(sc[ni], qah[ks], bh[ni]);
                MMA_BF16(sc[ni], qal[ks], bh[ni]);
                MMA_BF16(sc[ni], qah[ks], bl[ni]);
            }
        }
#pragma unroll
        for (int ni = 0; ni < 4; ni++) {
            int col = wn + ni*8 + tc;
            *(float2*)&Ss[(wm + g    )*PADS + col] = make_float2(sc[ni][0], sc[ni][1]);
            *(float2*)&Ss[(wm + g + 8)*PADS + col] = make_float2(sc[ni][2], sc[ni][3]);
        }
        __syncthreads();

        // ---- softmax + relational bias (scalar stage) ----
        float s[4][4];
#pragma unroll
        for (int r = 0; r < 4; r++) {
            float4 f = *(const float4*)&Ss[(ty*4+r)*PADS + tx*4];
            s[r][0] = f.x; s[r][1] = f.y; s[r][2] = f.z; s[r][3] = f.w;
        }
#pragma unroll
        for (int c = 0; c < 4; c++) {
            int j = tx*4 + c;
            float ej0 = Ejs[j*3+0];
            float ej1 = Ejs[j*3+1];
            float ej2 = Ejs[j*3+2];
#pragma unroll
            for (int r = 0; r < 4; r++) {
                float num = fi[r][0]*ej0 + fi[r][1]*ej1 + fi[r][2]*ej2;
                float den = eiw[r][0]*ej0 + eiw[r][1]*ej1 + eiw[r][2]*ej2;
                s[r][c] += num * __frcp_rn(den);
            }
        }
#pragma unroll
        for (int r = 0; r < 4; r++) {
            float mx = fmaxf(fmaxf(s[r][0], s[r][1]), fmaxf(s[r][2], s[r][3]));
#pragma unroll
            for (int o = 1; o < 16; o <<= 1)
                mx = fmaxf(mx, __shfl_xor_sync(0xffffffffu, mx, o));
            float mn   = fmaxf(mrow[r], mx);
            float corr = __expf(mrow[r] - mn);
            float p0 = __expf(s[r][0] - mn);
            float p1 = __expf(s[r][1] - mn);
            float p2 = __expf(s[r][2] - mn);
            float p3 = __expf(s[r][3] - mn);
            float rs = p0 + p1 + p2 + p3;
#pragma unroll
            for (int o = 1; o < 16; o <<= 1)
                rs += __shfl_xor_sync(0xffffffffu, rs, o);
            lrow[r] = lrow[r]*corr + rs;
            mrow[r] = mn;
            if (tx == 0) corrbuf[ty*4 + r] = corr;
            __nv_bfloat16 h0 = __float2bfloat16_rn(p0);
            __nv_bfloat16 h1 = __float2bfloat16_rn(p1);
            __nv_bfloat16 h2 = __float2bfloat16_rn(p2);
            __nv_bfloat16 h3 = __float2bfloat16_rn(p3);
            __nv_bfloat16 l0 = __float2bfloat16_rn(p0 - __bfloat162float(h0));
            __nv_bfloat16 l1 = __float2bfloat16_rn(p1 - __bfloat162float(h1));
            __nv_bfloat16 l2 = __float2bfloat16_rn(p2 - __bfloat162float(h2));
            __nv_bfloat16 l3 = __float2bfloat16_rn(p3 - __bfloat162float(h3));
            *(uint2*)&Ph[(ty*4+r)*BSTR + tx*4] =
                make_uint2(pack_bf16(h0, h1), pack_bf16(h2, h3));
            *(uint2*)&Pl[(ty*4+r)*BSTR + tx*4] =
                make_uint2(pack_bf16(l0, l1), pack_bf16(l2, l3));
        }
        __syncthreads();

        // ---- O = O*corr + P V (P a-frags like sgemm A, Vt b-frags) ----
        float c0 = corrbuf[wm + g];
        float c1 = corrbuf[wm + g + 8];
#pragma unroll
        for (int ni = 0; ni < 4; ni++) {
            acc[ni][0] *= c0; acc[ni][1] *= c0;
            acc[ni][2] *= c1; acc[ni][3] *= c1;
        }
#pragma unroll
        for (int ks = 0; ks < 4; ks++) {
            int k0 = ks * 16;
            unsigned pah[4], pal[4], vh[4][2], vl[4][2];
            pah[0] = *(const unsigned*)&Ph[(wm + g    )*BSTR + k0 + tc    ];
            pah[1] = *(const unsigned*)&Ph[(wm + g + 8)*BSTR + k0 + tc    ];
            pah[2] = *(const unsigned*)&Ph[(wm + g    )*BSTR + k0 + tc + 8];
            pah[3] = *(const unsigned*)&Ph[(wm + g + 8)*BSTR + k0 + tc + 8];
            pal[0] = *(const unsigned*)&Pl[(wm + g    )*BSTR + k0 + tc    ];
            pal[1] = *(const unsigned*)&Pl[(wm + g + 8)*BSTR + k0 + tc    ];
            pal[2] = *(const unsigned*)&Pl[(wm + g    )*BSTR + k0 + tc + 8];
            pal[3] = *(const unsigned*)&Pl[(wm + g + 8)*BSTR + k0 + tc + 8];
#pragma unroll
            for (int ni = 0; ni < 4; ni++) {
                int d = wn + ni * 8 + g;
                vh[ni][0] = *(const unsigned*)&Vth[d*VSTR + k0 + tc    ];
                vh[ni][1] = *(const unsigned*)&Vth[d*VSTR + k0 + tc + 8];
                vl[ni][0] = *(const unsigned*)&Vtl[d*VSTR + k0 + tc    ];
                vl[ni][1] = *(const unsigned*)&Vtl[d*VSTR + k0 + tc + 8];
            }
#pragma unroll
            for (int ni = 0; ni < 4; ni++) {
                MMA_BF16(acc[ni], pah, vh[ni]);
                MMA_BF16(acc[ni], pal, vh[ni]);
                MMA_BF16(acc[ni], pah, vl[ni]);
            }
        }
    }

    // ---- epilogue: publish row sums, normalize, store ----
    __syncthreads();
    if (tx == 0) {
#pragma unroll
        for (int r = 0; r < 4; r++) corrbuf[ty*4 + r] = lrow[r];
    }
    __syncthreads();

    float inv0 = __frcp_rn(corrbuf[wm + g]);
    float inv1 = __frcp_rn(corrbuf[wm + g + 8]);
    size_t r0 = (size_t)(bb*SEQ + i0 + wm + g);
#pragma unroll
    for (int ni = 0; ni < 4; ni++) {
        int col = hh*HD + wn + ni*8 + tc;
        *(float2*)(g_ctx + r0*DIM + col) =
            make_float2(acc[ni][0]*inv0, acc[ni][1]*inv0);
        *(float2*)(g_ctx + (r0+8)*DIM + col) =
            make_float2(acc[ni][2]*inv1, acc[ni][3]*inv1);
    }
}

// ---------------- launcher ----------------
extern "C" void kernel_launch(void* const* d_in, const int* in_sizes, int n_in,
                              void* d_out, int out_size)
{
    (void)in_sizes; (void)n_in; (void)out_size;
    const float* x    = (const float*)d_in[0];
    const float* Wq   = (const float*)d_in[1];
    const float* bq   = (const float*)d_in[2];
    const float* Wk   = (const float*)d_in[3];
    const float* bk   = (const float*)d_in[4];
    const float* Wv   = (const float*)d_in[5];
    const float* bv   = (const float*)d_in[6];
    const float* Wo   = (const float*)d_in[7];
    const float* bo   = (const float*)d_in[8];
    const float* relW = (const float*)d_in[9];
    const float* relb = (const float*)d_in[10];
    const float* lb   = (const float*)d_in[11];
    const float* gW   = (const float*)d_in[12];
    const float* gb   = (const float*)d_in[13];

    float *q, *k, *v, *ctx;
    cudaGetSymbolAddress((void**)&q,   g_q);
    cudaGetSymbolAddress((void**)&k,   g_k);
    cudaGetSymbolAddress((void**)&v,   g_v);
    cudaGetSymbolAddress((void**)&ctx, g_ctx);

    cudaFuncSetAttribute(attn_mma,
                         cudaFuncAttributeMaxDynamicSharedMemorySize, ATTN_SMEM);

    dim3 ggrid(DIM/128, MROWS/128);
    sgemm_bf16x3<<<ggrid, 256>>>(x, Wq, bq, q, MROWS, DIM, DIM);
    sgemm_bf16x3<<<ggrid, 256>>>(x, Wk, bk, k, MROWS, DIM, DIM);
    sgemm_bf16x3<<<ggrid, 256>>>(x, Wv, bv, v, MROWS, DIM, DIM);
    proj_small<<<MROWS, 256>>>(x, relW, relb, gW, gb);

    attn_mma<<<dim3(SEQ/64, HEADS, BATCH), 256, ATTN_SMEM>>>(lb);

    sgemm_bf16x3<<<ggrid, 256>>>(ctx, Wo, bo, (float*)d_out, MROWS, DIM, DIM);
}

// round 7
// speedup vs baseline: 1.6881x; 1.0030x over previous
#include <cuda_runtime.h>
#include <cuda_bf16.h>
#include <math.h>

#define BATCH 2
#define SEQ   2048
#define DIM   1024
#define HEADS 16
#define HD    64
#define MROWS (BATCH*SEQ)

// ---------------- scratch (device globals: allocation-free) ----------------
__device__ float g_q[MROWS*DIM];
__device__ float g_k[MROWS*DIM];
__device__ float g_v[MROWS*DIM];
__device__ float g_ctx[MROWS*DIM];
__device__ float g_ei[MROWS*3];
__device__ float g_ej[MROWS*3];
__device__ float g_gate[MROWS*HEADS];

// ---------------- helpers (R2-proven set only) ----------------
__device__ __forceinline__ unsigned pack_bf16(__nv_bfloat16 a, __nv_bfloat16 b) {
    return (unsigned)__bfloat16_as_ushort(a) | ((unsigned)__bfloat16_as_ushort(b) << 16);
}

#define MMA_BF16(c, a, b) \
    asm volatile("mma.sync.aligned.m16n8k16.row.col.f32.bf16.bf16.f32 " \
                 "{%0,%1,%2,%3}, {%4,%5,%6,%7}, {%8,%9}, {%0,%1,%2,%3};" \
                 : "+f"(c[0]), "+f"(c[1]), "+f"(c[2]), "+f"(c[3]) \
                 : "r"(a[0]), "r"(a[1]), "r"(a[2]), "r"(a[3]), "r"(b[0]), "r"(b[1]))

// ============================================================================
// GEMM: C = A @ W^T + bias  (exact R2 kernel)
// ============================================================================
#define SSTR 40

__global__ __launch_bounds__(256) void sgemm_bf16x3(
    const float* __restrict__ A, const float* __restrict__ W,
    const float* __restrict__ bias, float* __restrict__ C,
    int M, int N, int K)
{
    __shared__ __nv_bfloat16 sAh[128][SSTR];
    __shared__ __nv_bfloat16 sAl[128][SSTR];
    __shared__ __nv_bfloat16 sBh[128][SSTR];
    __shared__ __nv_bfloat16 sBl[128][SSTR];

    const int bm = blockIdx.y * 128;
    const int bn = blockIdx.x * 128;
    const int tid = threadIdx.x;
    const int lane = tid & 31;
    const int w = tid >> 5;
    const int wm = (w >> 2) * 64;
    const int wn = (w & 3) * 32;
    const int g  = lane >> 2;
    const int tc = (lane & 3) * 2;
    const int tr  = tid >> 3;
    const int tc4 = (tid & 7) * 4;

    const float* Aptr = A + (size_t)(bm + tr) * K + tc4;
    const float* Wptr = W + (size_t)(bn + tr) * K + tc4;

    float acc[4][4][4];
#pragma unroll
    for (int mi = 0; mi < 4; mi++)
#pragma unroll
        for (int ni = 0; ni < 4; ni++)
#pragma unroll
            for (int c = 0; c < 4; c++) acc[mi][ni][c] = 0.f;

    float4 ra[4], rb[4];
#pragma unroll
    for (int i = 0; i < 4; i++) {
        ra[i] = *(const float4*)(Aptr + (size_t)(i * 32) * K);
        rb[i] = *(const float4*)(Wptr + (size_t)(i * 32) * K);
    }

    for (int k0 = 0; k0 < K; k0 += 32) {
#pragma unroll
        for (int i = 0; i < 4; i++) {
            int row = tr + i * 32;
            float vv[4] = {ra[i].x, ra[i].y, ra[i].z, ra[i].w};
            __nv_bfloat16 h[4], l[4];
#pragma unroll
            for (int j = 0; j < 4; j++) {
                h[j] = __float2bfloat16_rn(vv[j]);
                l[j] = __float2bfloat16_rn(vv[j] - __bfloat162float(h[j]));
            }
            *(uint2*)&sAh[row][tc4] = make_uint2(pack_bf16(h[0], h[1]), pack_bf16(h[2], h[3]));
            *(uint2*)&sAl[row][tc4] = make_uint2(pack_bf16(l[0], l[1]), pack_bf16(l[2], l[3]));

            float wv[4] = {rb[i].x, rb[i].y, rb[i].z, rb[i].w};
#pragma unroll
            for (int j = 0; j < 4; j++) {
                h[j] = __float2bfloat16_rn(wv[j]);
                l[j] = __float2bfloat16_rn(wv[j] - __bfloat162float(h[j]));
            }
            *(uint2*)&sBh[row][tc4] = make_uint2(pack_bf16(h[0], h[1]), pack_bf16(h[2], h[3]));
            *(uint2*)&sBl[row][tc4] = make_uint2(pack_bf16(l[0], l[1]), pack_bf16(l[2], l[3]));
        }
        __syncthreads();

        if (k0 + 32 < K) {
#pragma unroll
            for (int i = 0; i < 4; i++) {
                ra[i] = *(const float4*)(Aptr + k0 + 32 + (size_t)(i * 32) * K);
                rb[i] = *(const float4*)(Wptr + k0 + 32 + (size_t)(i * 32) * K);
            }
        }

#pragma unroll
        for (int ks = 0; ks < 32; ks += 16) {
            unsigned ah[4][4], al[4][4], bh[4][2], bl[4][2];
#pragma unroll
            for (int mi = 0; mi < 4; mi++) {
                int r = wm + mi * 16;
                ah[mi][0] = *(const unsigned*)&sAh[r + g    ][ks + tc    ];
                ah[mi][1] = *(const unsigned*)&sAh[r + g + 8][ks + tc    ];
                ah[mi][2] = *(const unsigned*)&sAh[r + g    ][ks + tc + 8];
                ah[mi][3] = *(const unsigned*)&sAh[r + g + 8][ks + tc + 8];
                al[mi][0] = *(const unsigned*)&sAl[r + g    ][ks + tc    ];
                al[mi][1] = *(const unsigned*)&sAl[r + g + 8][ks + tc    ];
                al[mi][2] = *(const unsigned*)&sAl[r + g    ][ks + tc + 8];
                al[mi][3] = *(const unsigned*)&sAl[r + g + 8][ks + tc + 8];
            }
#pragma unroll
            for (int ni = 0; ni < 4; ni++) {
                int n = wn + ni * 8 + g;
                bh[ni][0] = *(const unsigned*)&sBh[n][ks + tc    ];
                bh[ni][1] = *(const unsigned*)&sBh[n][ks + tc + 8];
                bl[ni][0] = *(const unsigned*)&sBl[n][ks + tc    ];
                bl[ni][1] = *(const unsigned*)&sBl[n][ks + tc + 8];
            }
#pragma unroll
            for (int mi = 0; mi < 4; mi++)
#pragma unroll
                for (int ni = 0; ni < 4; ni++) {
                    MMA_BF16(acc[mi][ni], ah[mi], bh[ni]);
                    MMA_BF16(acc[mi][ni], al[mi], bh[ni]);
                    MMA_BF16(acc[mi][ni], ah[mi], bl[ni]);
                }
        }
        __syncthreads();
    }

#pragma unroll
    for (int mi = 0; mi < 4; mi++) {
        int r0 = bm + wm + mi * 16 + g;
#pragma unroll
        for (int ni = 0; ni < 4; ni++) {
            int c0 = bn + wn + ni * 8 + tc;
            float2 bb = *(const float2*)&bias[c0];
            float2 o0 = make_float2(acc[mi][ni][0] + bb.x, acc[mi][ni][1] + bb.y);
            float2 o1 = make_float2(acc[mi][ni][2] + bb.x, acc[mi][ni][3] + bb.y);
            *(float2*)(C + (size_t)r0 * N + c0)       = o0;
            *(float2*)(C + (size_t)(r0 + 8) * N + c0) = o1;
        }
    }
}

// ---------------- small projections (R2-proven) ----------------
__global__ __launch_bounds__(256) void proj_small(
    const float* __restrict__ x,
    const float* __restrict__ relW, const float* __restrict__ relb,
    const float* __restrict__ gW,   const float* __restrict__ gb)
{
    __shared__ float xs[DIM];
    const int m = blockIdx.x;
    const float* xrow = x + (size_t)m * DIM;
    for (int i = threadIdx.x; i < DIM; i += 256) xs[i] = xrow[i];
    __syncthreads();

    const int warp = threadIdx.x >> 5;
    const int lane = threadIdx.x & 31;
    for (int o = warp; o < 22; o += 8) {
        const float* wp;
        if (o < 3)       wp = relW + (size_t)o * (2*DIM);
        else if (o < 6)  wp = relW + (size_t)(o-3) * (2*DIM) + DIM;
        else             wp = gW   + (size_t)(o-6) * DIM;
        float s = 0.f;
        for (int k = lane; k < DIM; k += 32) s += xs[k] * wp[k];
#pragma unroll
        for (int off = 16; off; off >>= 1) s += __shfl_xor_sync(0xffffffffu, s, off);
        if (lane == 0) {
            if (o < 3)      g_ei[(size_t)m*3 + o]      = expf(s + relb[o]);
            else if (o < 6) g_ej[(size_t)m*3 + (o-3)]  = expf(s);
            else            g_gate[(size_t)m*HEADS + (o-6)] =
                                1.f / (1.f + expf(-(s + gb[o-6])));
        }
    }
}

// ============================================================================
// Fused flash-attention: i-tile 128, warp owns 16 rows x all 64 cols.
// S and P register-resident; no Ss/P smem round trips; 2 syncs per j-tile.
// ============================================================================
#define BSTR 72
#define VSTR 72
#define ATTN_SMEM ((2*128*BSTR + 2*64*BSTR + 2*64*VSTR)*2 + 192*4)

__global__ __launch_bounds__(256, 1) void attn_mma(const float* __restrict__ lb)
{
    extern __shared__ __nv_bfloat16 smb[];
    __nv_bfloat16* Qh  = smb;
    __nv_bfloat16* Ql  = Qh  + 128*BSTR;
    __nv_bfloat16* Kh  = Ql  + 128*BSTR;
    __nv_bfloat16* Kl  = Kh  + 64*BSTR;
    __nv_bfloat16* Vth = Kl  + 64*BSTR;
    __nv_bfloat16* Vtl = Vth + 64*VSTR;
    float* Ejs = (float*)(Vtl + 64*VSTR);

    const int bb = blockIdx.z;
    const int hh = blockIdx.y;
    const int i0 = blockIdx.x * 128;
    const int tid  = threadIdx.x;
    const int lane = tid & 31;
    const int w    = tid >> 5;
    const int wm = w * 16;            // warp rows wm..wm+15 of the 128-row tile
    const int g  = lane >> 2;
    const int tc = (lane & 3) * 2;
    const int r0 = wm + g;            // this thread's two rows
    const int r1 = wm + g + 8;

    // ---- Q tile fill: 128 rows, scale 1/8, hi/lo split ----
    const float* qbase = g_q + ((size_t)(bb*SEQ + i0))*DIM + hh*HD;
    for (int t = tid; t < 128*16; t += 256) {
        int i = t >> 4;
        int k4 = (t & 15) << 2;
        float4 qv = *(const float4*)(qbase + (size_t)i*DIM + k4);
        float vv[4] = {qv.x*0.125f, qv.y*0.125f, qv.z*0.125f, qv.w*0.125f};
        __nv_bfloat16 h[4], l[4];
#pragma unroll
        for (int j = 0; j < 4; j++) {
            h[j] = __float2bfloat16_rn(vv[j]);
            l[j] = __float2bfloat16_rn(vv[j] - __bfloat162float(h[j]));
        }
        *(uint2*)&Qh[i*BSTR + k4] = make_uint2(pack_bf16(h[0], h[1]), pack_bf16(h[2], h[3]));
        *(uint2*)&Ql[i*BSTR + k4] = make_uint2(pack_bf16(l[0], l[1]), pack_bf16(l[2], l[3]));
    }

    // ---- per-thread relational constants for rows r0, r1 ----
    const float lb0 = lb[hh*3+0];
    const float lb1 = lb[hh*3+1];
    const float lb2 = lb[hh*3+2];
    float fi0[3], ei0[3], fi1[3], ei1[3];
    {
        int gi0 = bb*SEQ + i0 + r0;
        int gi1 = bb*SEQ + i0 + r1;
        float gg0 = g_gate[(size_t)gi0*HEADS + hh];
        float gg1 = g_gate[(size_t)gi1*HEADS + hh];
#pragma unroll
        for (int kk = 0; kk < 3; kk++) {
            ei0[kk] = g_ei[(size_t)gi0*3 + kk];
            ei1[kk] = g_ei[(size_t)gi1*3 + kk];
        }
        fi0[0] = gg0*ei0[0]*lb0; fi0[1] = gg0*ei0[1]*lb1; fi0[2] = gg0*ei0[2]*lb2;
        fi1[0] = gg1*ei1[0]*lb0; fi1[1] = gg1*ei1[1]*lb1; fi1[2] = gg1*ei1[2]*lb2;
    }
    __syncthreads();

    // ---- Q a-fragments (j-invariant) ----
    unsigned qah[4][4], qal[4][4];
#pragma unroll
    for (int ks = 0; ks < 4; ks++) {
        int k0 = ks * 16;
        qah[ks][0] = *(const unsigned*)&Qh[r0*BSTR + k0 + tc    ];
        qah[ks][1] = *(const unsigned*)&Qh[r1*BSTR + k0 + tc    ];
        qah[ks][2] = *(const unsigned*)&Qh[r0*BSTR + k0 + tc + 8];
        qah[ks][3] = *(const unsigned*)&Qh[r1*BSTR + k0 + tc + 8];
        qal[ks][0] = *(const unsigned*)&Ql[r0*BSTR + k0 + tc    ];
        qal[ks][1] = *(const unsigned*)&Ql[r1*BSTR + k0 + tc    ];
        qal[ks][2] = *(const unsigned*)&Ql[r0*BSTR + k0 + tc + 8];
        qal[ks][3] = *(const unsigned*)&Ql[r1*BSTR + k0 + tc + 8];
    }

    float acc[8][4];
#pragma unroll
    for (int ni = 0; ni < 8; ni++)
#pragma unroll
        for (int c = 0; c < 4; c++) acc[ni][c] = 0.f;
    float m0 = -1e30f, m1 = -1e30f;
    float l0 = 0.f, l1 = 0.f;

    const float* kbase = g_k + ((size_t)(bb*SEQ))*DIM + hh*HD;
    const float* vbase = g_v + ((size_t)(bb*SEQ))*DIM + hh*HD;

    for (int jt = 0; jt < SEQ/64; jt++) {
        const int j0 = jt * 64;
        __syncthreads();   // prev-iter K/V readers done before overwrite

        // ---- K fill [j][d] + V fill transposed [d][j], hi/lo split ----
        for (int t = tid; t < 64*16; t += 256) {
            int j = t >> 4;
            int k4 = (t & 15) << 2;
            float4 kv = *(const float4*)(kbase + (size_t)(j0+j)*DIM + k4);
            float vv[4] = {kv.x, kv.y, kv.z, kv.w};
            __nv_bfloat16 h[4], l[4];
#pragma unroll
            for (int jj = 0; jj < 4; jj++) {
                h[jj] = __float2bfloat16_rn(vv[jj]);
                l[jj] = __float2bfloat16_rn(vv[jj] - __bfloat162float(h[jj]));
            }
            *(uint2*)&Kh[j*BSTR + k4] = make_uint2(pack_bf16(h[0], h[1]), pack_bf16(h[2], h[3]));
            *(uint2*)&Kl[j*BSTR + k4] = make_uint2(pack_bf16(l[0], l[1]), pack_bf16(l[2], l[3]));

            float4 vvec = *(const float4*)(vbase + (size_t)(j0+j)*DIM + k4);
            float vw[4] = {vvec.x, vvec.y, vvec.z, vvec.w};
#pragma unroll
            for (int jj = 0; jj < 4; jj++) {
                __nv_bfloat16 vh = __float2bfloat16_rn(vw[jj]);
                __nv_bfloat16 vl = __float2bfloat16_rn(vw[jj] - __bfloat162float(vh));
                Vth[(k4 + jj)*VSTR + j] = vh;
                Vtl[(k4 + jj)*VSTR + j] = vl;
            }
        }
        for (int t = tid; t < 64*3; t += 256) {
            Ejs[t] = g_ej[((size_t)(bb*SEQ + j0))*3 + t];
        }
        __syncthreads();

        // ---- S = Q K^T into registers (warp covers all 8 n-tiles) ----
        float sc[8][4];
#pragma unroll
        for (int ni = 0; ni < 8; ni++)
#pragma unroll
            for (int c = 0; c < 4; c++) sc[ni][c] = 0.f;
#pragma unroll
        for (int ks = 0; ks < 4; ks++) {
            int k0 = ks * 16;
#pragma unroll
            for (int ni = 0; ni < 8; ni++) {
                int n = ni * 8 + g;
                unsigned bh[2], bl[2];
                bh[0] = *(const unsigned*)&Kh[n*BSTR + k0 + tc    ];
                bh[1] = *(const unsigned*)&Kh[n*BSTR + k0 + tc + 8];
                bl[0] = *(const unsigned*)&Kl[n*BSTR + k0 + tc    ];
                bl[1] = *(const unsigned*)&Kl[n*BSTR + k0 + tc + 8];
                MMA_BF16(sc[ni], qah[ks], bh);
                MMA_BF16(sc[ni], qal[ks], bh);
                MMA_BF16(sc[ni], qah[ks], bl);
            }
        }

        // ---- relational bias (register-resident) ----
#pragma unroll
        for (int ni = 0; ni < 8; ni++) {
            int j = ni*8 + tc;
            float ea0 = Ejs[j*3+0], ea1 = Ejs[j*3+1], ea2 = Ejs[j*3+2];
            float eb0 = Ejs[j*3+3], eb1 = Ejs[j*3+4], eb2 = Ejs[j*3+5];
            sc[ni][0] += (fi0[0]*ea0 + fi0[1]*ea1 + fi0[2]*ea2)
                       * __frcp_rn(ei0[0]*ea0 + ei0[1]*ea1 + ei0[2]*ea2);
            sc[ni][1] += (fi0[0]*eb0 + fi0[1]*eb1 + fi0[2]*eb2)
                       * __frcp_rn(ei0[0]*eb0 + ei0[1]*eb1 + ei0[2]*eb2);
            sc[ni][2] += (fi1[0]*ea0 + fi1[1]*ea1 + fi1[2]*ea2)
                       * __frcp_rn(ei1[0]*ea0 + ei1[1]*ea1 + ei1[2]*ea2);
            sc[ni][3] += (fi1[0]*eb0 + fi1[1]*eb1 + fi1[2]*eb2)
                       * __frcp_rn(ei1[0]*eb0 + ei1[1]*eb1 + ei1[2]*eb2);
        }

        // ---- warp-local online softmax (quad reductions) ----
        float mx0 = -1e30f, mx1 = -1e30f;
#pragma unroll
        for (int ni = 0; ni < 8; ni++) {
            mx0 = fmaxf(mx0, fmaxf(sc[ni][0], sc[ni][1]));
            mx1 = fmaxf(mx1, fmaxf(sc[ni][2], sc[ni][3]));
        }
        mx0 = fmaxf(mx0, __shfl_xor_sync(0xffffffffu, mx0, 1));
        mx0 = fmaxf(mx0, __shfl_xor_sync(0xffffffffu, mx0, 2));
        mx1 = fmaxf(mx1, __shfl_xor_sync(0xffffffffu, mx1, 1));
        mx1 = fmaxf(mx1, __shfl_xor_sync(0xffffffffu, mx1, 2));
        float mn0 = fmaxf(m0, mx0);
        float mn1 = fmaxf(m1, mx1);
        float corr0 = __expf(m0 - mn0);
        float corr1 = __expf(m1 - mn1);

        float rs0 = 0.f, rs1 = 0.f;
        unsigned ph[8][2], pl[8][2];
#pragma unroll
        for (int ni = 0; ni < 8; ni++) {
            float p0 = __expf(sc[ni][0] - mn0);
            float p1 = __expf(sc[ni][1] - mn0);
            float p2 = __expf(sc[ni][2] - mn1);
            float p3 = __expf(sc[ni][3] - mn1);
            rs0 += p0 + p1;
            rs1 += p2 + p3;
            __nv_bfloat16 h0 = __float2bfloat16_rn(p0);
            __nv_bfloat16 h1 = __float2bfloat16_rn(p1);
            __nv_bfloat16 h2 = __float2bfloat16_rn(p2);
            __nv_bfloat16 h3 = __float2bfloat16_rn(p3);
            ph[ni][0] = pack_bf16(h0, h1);
            ph[ni][1] = pack_bf16(h2, h3);
            pl[ni][0] = pack_bf16(__float2bfloat16_rn(p0 - __bfloat162float(h0)),
                                  __float2bfloat16_rn(p1 - __bfloat162float(h1)));
            pl[ni][1] = pack_bf16(__float2bfloat16_rn(p2 - __bfloat162float(h2)),
                                  __float2bfloat16_rn(p3 - __bfloat162float(h3)));
        }
        rs0 += __shfl_xor_sync(0xffffffffu, rs0, 1);
        rs0 += __shfl_xor_sync(0xffffffffu, rs0, 2);
        rs1 += __shfl_xor_sync(0xffffffffu, rs1, 1);
        rs1 += __shfl_xor_sync(0xffffffffu, rs1, 2);
        l0 = l0*corr0 + rs0;
        l1 = l1*corr1 + rs1;
        m0 = mn0;
        m1 = mn1;

        // ---- O = O*corr + P V (P a-frags direct from registers) ----
#pragma unroll
        for (int ni = 0; ni < 8; ni++) {
            acc[ni][0] *= corr0; acc[ni][1] *= corr0;
            acc[ni][2] *= corr1; acc[ni][3] *= corr1;
        }
#pragma unroll
        for (int ks = 0; ks < 4; ks++) {
            int k0 = ks * 16;
            unsigned pah[4], pal[4];
            pah[0] = ph[2*ks  ][0];
            pah[1] = ph[2*ks  ][1];
            pah[2] = ph[2*ks+1][0];
            pah[3] = ph[2*ks+1][1];
            pal[0] = pl[2*ks  ][0];
            pal[1] = pl[2*ks  ][1];
            pal[2] = pl[2*ks+1][0];
            pal[3] = pl[2*ks+1][1];
#pragma unroll
            for (int ni = 0; ni < 8; ni++) {
                int d = ni * 8 + g;
                unsigned vh[2], vl[2];
                vh[0] = *(const unsigned*)&Vth[d*VSTR + k0 + tc    ];
                vh[1] = *(const unsigned*)&Vth[d*VSTR + k0 + tc + 8];
                vl[0] = *(const unsigned*)&Vtl[d*VSTR + k0 + tc    ];
                vl[1] = *(const unsigned*)&Vtl[d*VSTR + k0 + tc + 8];
                MMA_BF16(acc[ni], pah, vh);
                MMA_BF16(acc[ni], pal, vh);
                MMA_BF16(acc[ni], pah, vl);
            }
        }
    }

    // ---- epilogue: per-thread normalize, store ----
    float inv0 = __frcp_rn(l0);
    float inv1 = __frcp_rn(l1);
    size_t gr0 = (size_t)(bb*SEQ + i0 + r0);
    size_t gr1 = (size_t)(bb*SEQ + i0 + r1);
#pragma unroll
    for (int ni = 0; ni < 8; ni++) {
        int col = hh*HD + ni*8 + tc;
        *(float2*)(g_ctx + gr0*DIM + col) =
            make_float2(acc[ni][0]*inv0, acc[ni][1]*inv0);
        *(float2*)(g_ctx + gr1*DIM + col) =
            make_float2(acc[ni][2]*inv1, acc[ni][3]*inv1);
    }
}

// ---------------- launcher ----------------
extern "C" void kernel_launch(void* const* d_in, const int* in_sizes, int n_in,
                              void* d_out, int out_size)
{
    (void)in_sizes; (void)n_in; (void)out_size;
    const float* x    = (const float*)d_in[0];
    const float* Wq   = (const float*)d_in[1];
    const float* bq   = (const float*)d_in[2];
    const float* Wk   = (const float*)d_in[3];
    const float* bk   = (const float*)d_in[4];
    const float* Wv   = (const float*)d_in[5];
    const float* bv   = (const float*)d_in[6];
    const float* Wo   = (const float*)d_in[7];
    const float* bo   = (const float*)d_in[8];
    const float* relW = (const float*)d_in[9];
    const float* relb = (const float*)d_in[10];
    const float* lb   = (const float*)d_in[11];
    const float* gW   = (const float*)d_in[12];
    const float* gb   = (const float*)d_in[13];

    float *q, *k, *v, *ctx;
    cudaGetSymbolAddress((void**)&q,   g_q);
    cudaGetSymbolAddress((void**)&k,   g_k);
    cudaGetSymbolAddress((void**)&v,   g_v);
    cudaGetSymbolAddress((void**)&ctx, g_ctx);

    cudaFuncSetAttribute(attn_mma,
                         cudaFuncAttributeMaxDynamicSharedMemorySize, ATTN_SMEM);

    dim3 ggrid(DIM/128, MROWS/128);
    sgemm_bf16x3<<<ggrid, 256>>>(x, Wq, bq, q, MROWS, DIM, DIM);
    sgemm_bf16x3<<<ggrid, 256>>>(x, Wk, bk, k, MROWS, DIM, DIM);
    sgemm_bf16x3<<<ggrid, 256>>>(x, Wv, bv, v, MROWS, DIM, DIM);
    proj_small<<<MROWS, 256>>>(x, relW, relb, gW, gb);

    attn_mma<<<dim3(SEQ/128, HEADS, BATCH), 256, ATTN_SMEM>>>(lb);

    sgemm_bf16x3<<<ggrid, 256>>>(ctx, Wo, bo, (float*)d_out, MROWS, DIM, DIM);
}

// round 9
// speedup vs baseline: 1.9762x; 1.1707x over previous
#include <cuda_runtime.h>
#include <cuda_bf16.h>
#include <math.h>

#define BATCH 2
#define SEQ   2048
#define DIM   1024
#define HEADS 16
#define HD    64
#define MROWS (BATCH*SEQ)

// ---------------- scratch (device globals: allocation-free) ----------------
__device__ float g_q[MROWS*DIM];
__device__ float g_k[MROWS*DIM];
__device__ float g_v[MROWS*DIM];
__device__ float g_ctx[MROWS*DIM];
__device__ float g_ei[MROWS*3];
__device__ float g_ej[MROWS*3];
__device__ float g_gate[MROWS*HEADS];

// ---------------- helpers ----------------
__device__ __forceinline__ unsigned pack_bf16(__nv_bfloat16 a, __nv_bfloat16 b) {
    return (unsigned)__bfloat16_as_ushort(a) | ((unsigned)__bfloat16_as_ushort(b) << 16);
}

#define SMADDR(p) ((unsigned)__cvta_generic_to_shared(p))

#define MMA_BF16(c, a, b) \
    asm volatile("mma.sync.aligned.m16n8k16.row.col.f32.bf16.bf16.f32 " \
                 "{%0,%1,%2,%3}, {%4,%5,%6,%7}, {%8,%9}, {%0,%1,%2,%3};" \
                 : "+f"(c[0]), "+f"(c[1]), "+f"(c[2]), "+f"(c[3]) \
                 : "r"(a[0]), "r"(a[1]), "r"(a[2]), "r"(a[3]), "r"(b[0]), "r"(b[1]))

// ldmatrix macros: outputs are named scalar unsigned locals.
#define LDMX4(r0, r1, r2, r3, addr) \
    asm volatile("ldmatrix.sync.aligned.m8n8.x4.shared.b16 {%0,%1,%2,%3}, [%4];" \
                 : "=r"(r0), "=r"(r1), "=r"(r2), "=r"(r3) : "r"(addr))

#define LDMX4T(r0, r1, r2, r3, addr) \
    asm volatile("ldmatrix.sync.aligned.m8n8.x4.trans.shared.b16 {%0,%1,%2,%3}, [%4];" \
                 : "=r"(r0), "=r"(r1), "=r"(r2), "=r"(r3) : "r"(addr))

// ============================================================================
// GEMM: C = A @ W^T + bias  (exact R2 kernel, unchanged)
// ============================================================================
#define SSTR 40

__global__ __launch_bounds__(256) void sgemm_bf16x3(
    const float* __restrict__ A, const float* __restrict__ W,
    const float* __restrict__ bias, float* __restrict__ C,
    int M, int N, int K)
{
    __shared__ __nv_bfloat16 sAh[128][SSTR];
    __shared__ __nv_bfloat16 sAl[128][SSTR];
    __shared__ __nv_bfloat16 sBh[128][SSTR];
    __shared__ __nv_bfloat16 sBl[128][SSTR];

    const int bm = blockIdx.y * 128;
    const int bn = blockIdx.x * 128;
    const int tid = threadIdx.x;
    const int lane = tid & 31;
    const int w = tid >> 5;
    const int wm = (w >> 2) * 64;
    const int wn = (w & 3) * 32;
    const int g  = lane >> 2;
    const int tc = (lane & 3) * 2;
    const int tr  = tid >> 3;
    const int tc4 = (tid & 7) * 4;

    const float* Aptr = A + (size_t)(bm + tr) * K + tc4;
    const float* Wptr = W + (size_t)(bn + tr) * K + tc4;

    float acc[4][4][4];
#pragma unroll
    for (int mi = 0; mi < 4; mi++)
#pragma unroll
        for (int ni = 0; ni < 4; ni++)
#pragma unroll
            for (int c = 0; c < 4; c++) acc[mi][ni][c] = 0.f;

    float4 ra[4], rb[4];
#pragma unroll
    for (int i = 0; i < 4; i++) {
        ra[i] = *(const float4*)(Aptr + (size_t)(i * 32) * K);
        rb[i] = *(const float4*)(Wptr + (size_t)(i * 32) * K);
    }

    for (int k0 = 0; k0 < K; k0 += 32) {
#pragma unroll
        for (int i = 0; i < 4; i++) {
            int row = tr + i * 32;
            float vv[4] = {ra[i].x, ra[i].y, ra[i].z, ra[i].w};
            __nv_bfloat16 h[4], l[4];
#pragma unroll
            for (int j = 0; j < 4; j++) {
                h[j] = __float2bfloat16_rn(vv[j]);
                l[j] = __float2bfloat16_rn(vv[j] - __bfloat162float(h[j]));
            }
            *(uint2*)&sAh[row][tc4] = make_uint2(pack_bf16(h[0], h[1]), pack_bf16(h[2], h[3]));
            *(uint2*)&sAl[row][tc4] = make_uint2(pack_bf16(l[0], l[1]), pack_bf16(l[2], l[3]));

            float wv[4] = {rb[i].x, rb[i].y, rb[i].z, rb[i].w};
#pragma unroll
            for (int j = 0; j < 4; j++) {
                h[j] = __float2bfloat16_rn(wv[j]);
                l[j] = __float2bfloat16_rn(wv[j] - __bfloat162float(h[j]));
            }
            *(uint2*)&sBh[row][tc4] = make_uint2(pack_bf16(h[0], h[1]), pack_bf16(h[2], h[3]));
            *(uint2*)&sBl[row][tc4] = make_uint2(pack_bf16(l[0], l[1]), pack_bf16(l[2], l[3]));
        }
        __syncthreads();

        if (k0 + 32 < K) {
#pragma unroll
            for (int i = 0; i < 4; i++) {
                ra[i] = *(const float4*)(Aptr + k0 + 32 + (size_t)(i * 32) * K);
                rb[i] = *(const float4*)(Wptr + k0 + 32 + (size_t)(i * 32) * K);
            }
        }

#pragma unroll
        for (int ks = 0; ks < 32; ks += 16) {
            unsigned ah[4][4], al[4][4], bh[4][2], bl[4][2];
#pragma unroll
            for (int mi = 0; mi < 4; mi++) {
                int r = wm + mi * 16;
                ah[mi][0] = *(const unsigned*)&sAh[r + g    ][ks + tc    ];
                ah[mi][1] = *(const unsigned*)&sAh[r + g + 8][ks + tc    ];
                ah[mi][2] = *(const unsigned*)&sAh[r + g    ][ks + tc + 8];
                ah[mi][3] = *(const unsigned*)&sAh[r + g + 8][ks + tc + 8];
                al[mi][0] = *(const unsigned*)&sAl[r + g    ][ks + tc    ];
                al[mi][1] = *(const unsigned*)&sAl[r + g + 8][ks + tc    ];
                al[mi][2] = *(const unsigned*)&sAl[r + g    ][ks + tc + 8];
                al[mi][3] = *(const unsigned*)&sAl[r + g + 8][ks + tc + 8];
            }
#pragma unroll
            for (int ni = 0; ni < 4; ni++) {
                int n = wn + ni * 8 + g;
                bh[ni][0] = *(const unsigned*)&sBh[n][ks + tc    ];
                bh[ni][1] = *(const unsigned*)&sBh[n][ks + tc + 8];
                bl[ni][0] = *(const unsigned*)&sBl[n][ks + tc    ];
                bl[ni][1] = *(const unsigned*)&sBl[n][ks + tc + 8];
            }
#pragma unroll
            for (int mi = 0; mi < 4; mi++)
#pragma unroll
                for (int ni = 0; ni < 4; ni++) {
                    MMA_BF16(acc[mi][ni], ah[mi], bh[ni]);
                    MMA_BF16(acc[mi][ni], al[mi], bh[ni]);
                    MMA_BF16(acc[mi][ni], ah[mi], bl[ni]);
                }
        }
        __syncthreads();
    }

#pragma unroll
    for (int mi = 0; mi < 4; mi++) {
        int r0 = bm + wm + mi * 16 + g;
#pragma unroll
        for (int ni = 0; ni < 4; ni++) {
            int c0 = bn + wn + ni * 8 + tc;
            float2 bb = *(const float2*)&bias[c0];
            float2 o0 = make_float2(acc[mi][ni][0] + bb.x, acc[mi][ni][1] + bb.y);
            float2 o1 = make_float2(acc[mi][ni][2] + bb.x, acc[mi][ni][3] + bb.y);
            *(float2*)(C + (size_t)r0 * N + c0)       = o0;
            *(float2*)(C + (size_t)(r0 + 8) * N + c0) = o1;
        }
    }
}

// ---------------- small projections (unchanged) ----------------
__global__ __launch_bounds__(256) void proj_small(
    const float* __restrict__ x,
    const float* __restrict__ relW, const float* __restrict__ relb,
    const float* __restrict__ gW,   const float* __restrict__ gb)
{
    __shared__ float xs[DIM];
    const int m = blockIdx.x;
    const float* xrow = x + (size_t)m * DIM;
    for (int i = threadIdx.x; i < DIM; i += 256) xs[i] = xrow[i];
    __syncthreads();

    const int warp = threadIdx.x >> 5;
    const int lane = threadIdx.x & 31;
    for (int o = warp; o < 22; o += 8) {
        const float* wp;
        if (o < 3)       wp = relW + (size_t)o * (2*DIM);
        else if (o < 6)  wp = relW + (size_t)(o-3) * (2*DIM) + DIM;
        else             wp = gW   + (size_t)(o-6) * DIM;
        float s = 0.f;
        for (int k = lane; k < DIM; k += 32) s += xs[k] * wp[k];
#pragma unroll
        for (int off = 16; off; off >>= 1) s += __shfl_xor_sync(0xffffffffu, s, off);
        if (lane == 0) {
            if (o < 3)      g_ei[(size_t)m*3 + o]      = expf(s + relb[o]);
            else if (o < 6) g_ej[(size_t)m*3 + (o-3)]  = expf(s);
            else            g_gate[(size_t)m*HEADS + (o-6)] =
                                1.f / (1.f + expf(-(s + gb[o-6])));
        }
    }
}

// ============================================================================
// Fused flash-attention: i-tile 128, warp owns 16 rows x all 64 cols.
// K and V both natural [row][d]; fragments via ldmatrix (x4 / x4.trans).
// ============================================================================
#define BSTR 72
#define ATTN_SMEM ((2*128*BSTR + 2*64*BSTR + 2*64*BSTR)*2 + 192*4)

__global__ __launch_bounds__(256, 1) void attn_mma(const float* __restrict__ lb)
{
    extern __shared__ __nv_bfloat16 smb[];
    __nv_bfloat16* Qh = smb;
    __nv_bfloat16* Ql = Qh + 128*BSTR;
    __nv_bfloat16* Kh = Ql + 128*BSTR;
    __nv_bfloat16* Kl = Kh + 64*BSTR;
    __nv_bfloat16* Vh = Kl + 64*BSTR;
    __nv_bfloat16* Vl = Vh + 64*BSTR;
    float* Ejs = (float*)(Vl + 64*BSTR);

    const int bb = blockIdx.z;
    const int hh = blockIdx.y;
    const int i0 = blockIdx.x * 128;
    const int tid  = threadIdx.x;
    const int lane = tid & 31;
    const int w    = tid >> 5;
    const int wm = w * 16;
    const int g  = lane >> 2;
    const int tc = (lane & 3) * 2;
    const int r0 = wm + g;
    const int r1 = wm + g + 8;

    // ---- Q tile fill: 128 rows, scale 1/8, hi/lo split ----
    const float* qbase = g_q + ((size_t)(bb*SEQ + i0))*DIM + hh*HD;
    for (int t = tid; t < 128*16; t += 256) {
        int i = t >> 4;
        int k4 = (t & 15) << 2;
        float4 qv = *(const float4*)(qbase + (size_t)i*DIM + k4);
        float vv[4] = {qv.x*0.125f, qv.y*0.125f, qv.z*0.125f, qv.w*0.125f};
        __nv_bfloat16 h[4], l[4];
#pragma unroll
        for (int j = 0; j < 4; j++) {
            h[j] = __float2bfloat16_rn(vv[j]);
            l[j] = __float2bfloat16_rn(vv[j] - __bfloat162float(h[j]));
        }
        *(uint2*)&Qh[i*BSTR + k4] = make_uint2(pack_bf16(h[0], h[1]), pack_bf16(h[2], h[3]));
        *(uint2*)&Ql[i*BSTR + k4] = make_uint2(pack_bf16(l[0], l[1]), pack_bf16(l[2], l[3]));
    }

    // ---- per-thread relational constants for rows r0, r1 ----
    const float lb0 = lb[hh*3+0];
    const float lb1 = lb[hh*3+1];
    const float lb2 = lb[hh*3+2];
    float fi0[3], ei0[3], fi1[3], ei1[3];
    {
        int gi0 = bb*SEQ + i0 + r0;
        int gi1 = bb*SEQ + i0 + r1;
        float gg0 = g_gate[(size_t)gi0*HEADS + hh];
        float gg1 = g_gate[(size_t)gi1*HEADS + hh];
#pragma unroll
        for (int kk = 0; kk < 3; kk++) {
            ei0[kk] = g_ei[(size_t)gi0*3 + kk];
            ei1[kk] = g_ei[(size_t)gi1*3 + kk];
        }
        fi0[0] = gg0*ei0[0]*lb0; fi0[1] = gg0*ei0[1]*lb1; fi0[2] = gg0*ei0[2]*lb2;
        fi1[0] = gg1*ei1[0]*lb0; fi1[1] = gg1*ei1[1]*lb1; fi1[2] = gg1*ei1[2]*lb2;
    }
    __syncthreads();

    // ---- Q a-fragments (j-invariant) ----
    unsigned qah[4][4], qal[4][4];
#pragma unroll
    for (int ks = 0; ks < 4; ks++) {
        int k0 = ks * 16;
        qah[ks][0] = *(const unsigned*)&Qh[r0*BSTR + k0 + tc    ];
        qah[ks][1] = *(const unsigned*)&Qh[r1*BSTR + k0 + tc    ];
        qah[ks][2] = *(const unsigned*)&Qh[r0*BSTR + k0 + tc + 8];
        qah[ks][3] = *(const unsigned*)&Qh[r1*BSTR + k0 + tc + 8];
        qal[ks][0] = *(const unsigned*)&Ql[r0*BSTR + k0 + tc    ];
        qal[ks][1] = *(const unsigned*)&Ql[r1*BSTR + k0 + tc    ];
        qal[ks][2] = *(const unsigned*)&Ql[r0*BSTR + k0 + tc + 8];
        qal[ks][3] = *(const unsigned*)&Ql[r1*BSTR + k0 + tc + 8];
    }

    // ---- ldmatrix per-lane base offsets (bytes) ----
    const int l7  = lane & 7;
    const int lb3 = (lane >> 3) & 1;
    const int lb4 = (lane >> 4) & 1;
    const unsigned krow_off = (unsigned)(((l7 + lb4*8) * BSTR + lb3*8) * 2);
    const unsigned vrow_off = (unsigned)(((l7 + lb3*8) * BSTR + lb4*8) * 2);
    const unsigned Khb = SMADDR(Kh);
    const unsigned Klb = SMADDR(Kl);
    const unsigned Vhb = SMADDR(Vh);
    const unsigned Vlb = SMADDR(Vl);

    float acc[8][4];
#pragma unroll
    for (int ni = 0; ni < 8; ni++)
#pragma unroll
        for (int c = 0; c < 4; c++) acc[ni][c] = 0.f;
    float m0 = -1e30f, m1 = -1e30f;
    float l0 = 0.f, l1 = 0.f;

    const float* kbase = g_k + ((size_t)(bb*SEQ))*DIM + hh*HD;
    const float* vbase = g_v + ((size_t)(bb*SEQ))*DIM + hh*HD;

    for (int jt = 0; jt < SEQ/64; jt++) {
        const int j0 = jt * 64;
        __syncthreads();   // prev-iter K/V readers done before overwrite

        // ---- K and V fills, both natural [row][d], uint2 hi/lo stores ----
        for (int t = tid; t < 64*16; t += 256) {
            int j = t >> 4;
            int k4 = (t & 15) << 2;
            float4 kv = *(const float4*)(kbase + (size_t)(j0+j)*DIM + k4);
            float vv[4] = {kv.x, kv.y, kv.z, kv.w};
            __nv_bfloat16 h[4], l[4];
#pragma unroll
            for (int jj = 0; jj < 4; jj++) {
                h[jj] = __float2bfloat16_rn(vv[jj]);
                l[jj] = __float2bfloat16_rn(vv[jj] - __bfloat162float(h[jj]));
            }
            *(uint2*)&Kh[j*BSTR + k4] = make_uint2(pack_bf16(h[0], h[1]), pack_bf16(h[2], h[3]));
            *(uint2*)&Kl[j*BSTR + k4] = make_uint2(pack_bf16(l[0], l[1]), pack_bf16(l[2], l[3]));

            float4 vvec = *(const float4*)(vbase + (size_t)(j0+j)*DIM + k4);
            float vw[4] = {vvec.x, vvec.y, vvec.z, vvec.w};
#pragma unroll
            for (int jj = 0; jj < 4; jj++) {
                h[jj] = __float2bfloat16_rn(vw[jj]);
                l[jj] = __float2bfloat16_rn(vw[jj] - __bfloat162float(h[jj]));
            }
            *(uint2*)&Vh[j*BSTR + k4] = make_uint2(pack_bf16(h[0], h[1]), pack_bf16(h[2], h[3]));
            *(uint2*)&Vl[j*BSTR + k4] = make_uint2(pack_bf16(l[0], l[1]), pack_bf16(l[2], l[3]));
        }
        for (int t = tid; t < 64*3; t += 256) {
            Ejs[t] = g_ej[((size_t)(bb*SEQ + j0))*3 + t];
        }
        __syncthreads();

        // ---- S = Q K^T : K b-frags via ldmatrix.x4 ----
        float sc[8][4];
#pragma unroll
        for (int ni = 0; ni < 8; ni++)
#pragma unroll
            for (int c = 0; c < 4; c++) sc[ni][c] = 0.f;
#pragma unroll
        for (int ks = 0; ks < 4; ks++) {
#pragma unroll
            for (int np = 0; np < 4; np++) {
                unsigned kaddr = krow_off + (unsigned)(np*(16*BSTR*2) + ks*32);
                unsigned t0, t1, t2, t3, u0, u1, u2, u3;
                LDMX4(t0, t1, t2, t3, Khb + kaddr);
                LDMX4(u0, u1, u2, u3, Klb + kaddr);
                unsigned bh0[2] = {t0, t1};
                unsigned bh1[2] = {t2, t3};
                unsigned bl0[2] = {u0, u1};
                unsigned bl1[2] = {u2, u3};
                MMA_BF16(sc[2*np    ], qah[ks], bh0);
                MMA_BF16(sc[2*np    ], qal[ks], bh0);
                MMA_BF16(sc[2*np    ], qah[ks], bl0);
                MMA_BF16(sc[2*np + 1], qah[ks], bh1);
                MMA_BF16(sc[2*np + 1], qal[ks], bh1);
                MMA_BF16(sc[2*np + 1], qah[ks], bl1);
            }
        }

        // ---- relational bias (register-resident) ----
#pragma unroll
        for (int ni = 0; ni < 8; ni++) {
            int j = ni*8 + tc;
            float ea0 = Ejs[j*3+0], ea1 = Ejs[j*3+1], ea2 = Ejs[j*3+2];
            float eb0 = Ejs[j*3+3], eb1 = Ejs[j*3+4], eb2 = Ejs[j*3+5];
            sc[ni][0] += __fdividef(fi0[0]*ea0 + fi0[1]*ea1 + fi0[2]*ea2,
                                    ei0[0]*ea0 + ei0[1]*ea1 + ei0[2]*ea2);
            sc[ni][1] += __fdividef(fi0[0]*eb0 + fi0[1]*eb1 + fi0[2]*eb2,
                                    ei0[0]*eb0 + ei0[1]*eb1 + ei0[2]*eb2);
            sc[ni][2] += __fdividef(fi1[0]*ea0 + fi1[1]*ea1 + fi1[2]*ea2,
                                    ei1[0]*ea0 + ei1[1]*ea1 + ei1[2]*ea2);
            sc[ni][3] += __fdividef(fi1[0]*eb0 + fi1[1]*eb1 + fi1[2]*eb2,
                                    ei1[0]*eb0 + ei1[1]*eb1 + ei1[2]*eb2);
        }

        // ---- warp-local online softmax (quad reductions) ----
        float mx0 = -1e30f, mx1 = -1e30f;
#pragma unroll
        for (int ni = 0; ni < 8; ni++) {
            mx0 = fmaxf(mx0, fmaxf(sc[ni][0], sc[ni][1]));
            mx1 = fmaxf(mx1, fmaxf(sc[ni][2], sc[ni][3]));
        }
        mx0 = fmaxf(mx0, __shfl_xor_sync(0xffffffffu, mx0, 1));
        mx0 = fmaxf(mx0, __shfl_xor_sync(0xffffffffu, mx0, 2));
        mx1 = fmaxf(mx1, __shfl_xor_sync(0xffffffffu, mx1, 1));
        mx1 = fmaxf(mx1, __shfl_xor_sync(0xffffffffu, mx1, 2));
        float mn0 = fmaxf(m0, mx0);
        float mn1 = fmaxf(m1, mx1);
        float corr0 = __expf(m0 - mn0);
        float corr1 = __expf(m1 - mn1);

        float rs0 = 0.f, rs1 = 0.f;
        unsigned ph[8][2], pl[8][2];
#pragma unroll
        for (int ni = 0; ni < 8; ni++) {
            float p0 = __expf(sc[ni][0] - mn0);
            float p1 = __expf(sc[ni][1] - mn0);
            float p2 = __expf(sc[ni][2] - mn1);
            float p3 = __expf(sc[ni][3] - mn1);
            rs0 += p0 + p1;
            rs1 += p2 + p3;
            __nv_bfloat16 h0 = __float2bfloat16_rn(p0);
            __nv_bfloat16 h1 = __float2bfloat16_rn(p1);
            __nv_bfloat16 h2 = __float2bfloat16_rn(p2);
            __nv_bfloat16 h3 = __float2bfloat16_rn(p3);
            ph[ni][0] = pack_bf16(h0, h1);
            ph[ni][1] = pack_bf16(h2, h3);
            pl[ni][0] = pack_bf16(__float2bfloat16_rn(p0 - __bfloat162float(h0)),
                                  __float2bfloat16_rn(p1 - __bfloat162float(h1)));
            pl[ni][1] = pack_bf16(__float2bfloat16_rn(p2 - __bfloat162float(h2)),
                                  __float2bfloat16_rn(p3 - __bfloat162float(h3)));
        }
        rs0 += __shfl_xor_sync(0xffffffffu, rs0, 1);
        rs0 += __shfl_xor_sync(0xffffffffu, rs0, 2);
        rs1 += __shfl_xor_sync(0xffffffffu, rs1, 1);
        rs1 += __shfl_xor_sync(0xffffffffu, rs1, 2);
        l0 = l0*corr0 + rs0;
        l1 = l1*corr1 + rs1;
        m0 = mn0;
        m1 = mn1;

        // ---- O = O*corr + P V : V b-frags via ldmatrix.x4.trans ----
#pragma unroll
        for (int ni = 0; ni < 8; ni++) {
            acc[ni][0] *= corr0; acc[ni][1] *= corr0;
            acc[ni][2] *= corr1; acc[ni][3] *= corr1;
        }
#pragma unroll
        for (int ks = 0; ks < 4; ks++) {
            unsigned pah[4], pal[4];
            pah[0] = ph[2*ks  ][0];
            pah[1] = ph[2*ks  ][1];
            pah[2] = ph[2*ks+1][0];
            pah[3] = ph[2*ks+1][1];
            pal[0] = pl[2*ks  ][0];
            pal[1] = pl[2*ks  ][1];
            pal[2] = pl[2*ks+1][0];
            pal[3] = pl[2*ks+1][1];
#pragma unroll
            for (int np = 0; np < 4; np++) {
                unsigned vaddr = vrow_off + (unsigned)(ks*(16*BSTR*2) + np*32);
                unsigned t0, t1, t2, t3, u0, u1, u2, u3;
                LDMX4T(t0, t1, t2, t3, Vhb + vaddr);
                LDMX4T(u0, u1, u2, u3, Vlb + vaddr);
                unsigned vh0[2] = {t0, t1};
                unsigned vh1[2] = {t2, t3};
                unsigned vl0[2] = {u0, u1};
                unsigned vl1[2] = {u2, u3};
                MMA_BF16(acc[2*np    ], pah, vh0);
                MMA_BF16(acc[2*np    ], pal, vh0);
                MMA_BF16(acc[2*np    ], pah, vl0);
                MMA_BF16(acc[2*np + 1], pah, vh1);
                MMA_BF16(acc[2*np + 1], pal, vh1);
                MMA_BF16(acc[2*np + 1], pah, vl1);
            }
        }
    }

    // ---- epilogue: per-thread normalize, store ----
    float inv0 = __frcp_rn(l0);
    float inv1 = __frcp_rn(l1);
    size_t gr0 = (size_t)(bb*SEQ + i0 + r0);
    size_t gr1 = (size_t)(bb*SEQ + i0 + r1);
#pragma unroll
    for (int ni = 0; ni < 8; ni++) {
        int col = hh*HD + ni*8 + tc;
        *(float2*)(g_ctx + gr0*DIM + col) =
            make_float2(acc[ni][0]*inv0, acc[ni][1]*inv0);
        *(float2*)(g_ctx + gr1*DIM + col) =
            make_float2(acc[ni][2]*inv1, acc[ni][3]*inv1);
    }
}

// ---------------- launcher ----------------
extern "C" void kernel_launch(void* const* d_in, const int* in_sizes, int n_in,
                              void* d_out, int out_size)
{
    (void)in_sizes; (void)n_in; (void)out_size;
    const float* x    = (const float*)d_in[0];
    const float* Wq   = (const float*)d_in[1];
    const float* bq   = (const float*)d_in[2];
    const float* Wk   = (const float*)d_in[3];
    const float* bk   = (const float*)d_in[4];
    const float* Wv   = (const float*)d_in[5];
    const float* bv   = (const float*)d_in[6];
    const float* Wo   = (const float*)d_in[7];
    const float* bo   = (const float*)d_in[8];
    const float* relW = (const float*)d_in[9];
    const float* relb = (const float*)d_in[10];
    const float* lb   = (const float*)d_in[11];
    const float* gW   = (const float*)d_in[12];
    const float* gb   = (const float*)d_in[13];

    float *q, *k, *v, *ctx;
    cudaGetSymbolAddress((void**)&q,   g_q);
    cudaGetSymbolAddress((void**)&k,   g_k);
    cudaGetSymbolAddress((void**)&v,   g_v);
    cudaGetSymbolAddress((void**)&ctx, g_ctx);

    cudaFuncSetAttribute(attn_mma,
                         cudaFuncAttributeMaxDynamicSharedMemorySize, ATTN_SMEM);

    dim3 ggrid(DIM/128, MROWS/128);
    sgemm_bf16x3<<<ggrid, 256>>>(x, Wq, bq, q, MROWS, DIM, DIM);
    sgemm_bf16x3<<<ggrid, 256>>>(x, Wk, bk, k, MROWS, DIM, DIM);
    sgemm_bf16x3<<<ggrid, 256>>>(x, Wv, bv, v, MROWS, DIM, DIM);
    proj_small<<<MROWS, 256>>>(x, relW, relb, gW, gb);

    attn_mma<<<dim3(SEQ/128, HEADS, BATCH), 256, ATTN_SMEM>>>(lb);

    sgemm_bf16x3<<<ggrid, 256>>>(ctx, Wo, bo, (float*)d_out, MROWS, DIM, DIM);
}

// round 10
// speedup vs baseline: 2.1880x; 1.1072x over previous
#include <cuda_runtime.h>
#include <cuda_bf16.h>
#include <math.h>

#define BATCH 2
#define SEQ   2048
#define DIM   1024
#define HEADS 16
#define HD    64
#define MROWS (BATCH*SEQ)

// ---------------- scratch (device globals: allocation-free) ----------------
__device__ __nv_bfloat16 g_qh[MROWS*DIM];
__device__ __nv_bfloat16 g_ql[MROWS*DIM];
__device__ __nv_bfloat16 g_kh[MROWS*DIM];
__device__ __nv_bfloat16 g_kl[MROWS*DIM];
__device__ __nv_bfloat16 g_vh[MROWS*DIM];
__device__ __nv_bfloat16 g_vl[MROWS*DIM];
__device__ float g_ctx[MROWS*DIM];
__device__ float g_ei[MROWS*3];
__device__ float g_ej[MROWS*3];
__device__ float g_gate[MROWS*HEADS];

// ---------------- helpers ----------------
__device__ __forceinline__ unsigned pack_bf16(__nv_bfloat16 a, __nv_bfloat16 b) {
    return (unsigned)__bfloat16_as_ushort(a) | ((unsigned)__bfloat16_as_ushort(b) << 16);
}

#define SMADDR(p) ((unsigned)__cvta_generic_to_shared(p))

#define MMA_BF16(c, a, b) \
    asm volatile("mma.sync.aligned.m16n8k16.row.col.f32.bf16.bf16.f32 " \
                 "{%0,%1,%2,%3}, {%4,%5,%6,%7}, {%8,%9}, {%0,%1,%2,%3};" \
                 : "+f"(c[0]), "+f"(c[1]), "+f"(c[2]), "+f"(c[3]) \
                 : "r"(a[0]), "r"(a[1]), "r"(a[2]), "r"(a[3]), "r"(b[0]), "r"(b[1]))

#define LDMX4(r0, r1, r2, r3, addr) \
    asm volatile("ldmatrix.sync.aligned.m8n8.x4.shared.b16 {%0,%1,%2,%3}, [%4];" \
                 : "=r"(r0), "=r"(r1), "=r"(r2), "=r"(r3) : "r"(addr))

#define LDMX4T(r0, r1, r2, r3, addr) \
    asm volatile("ldmatrix.sync.aligned.m8n8.x4.trans.shared.b16 {%0,%1,%2,%3}, [%4];" \
                 : "=r"(r0), "=r"(r1), "=r"(r2), "=r"(r3) : "r"(addr))

// ============================================================================
// GEMM core (R2-proven): C = A @ W^T + bias, fp32 out (used for Wo)
// ============================================================================
#define SSTR 40

__global__ __launch_bounds__(256) void sgemm_bf16x3(
    const float* __restrict__ A, const float* __restrict__ W,
    const float* __restrict__ bias, float* __restrict__ C,
    int M, int N, int K)
{
    __shared__ __nv_bfloat16 sAh[128][SSTR];
    __shared__ __nv_bfloat16 sAl[128][SSTR];
    __shared__ __nv_bfloat16 sBh[128][SSTR];
    __shared__ __nv_bfloat16 sBl[128][SSTR];

    const int bm = blockIdx.y * 128;
    const int bn = blockIdx.x * 128;
    const int tid = threadIdx.x;
    const int lane = tid & 31;
    const int w = tid >> 5;
    const int wm = (w >> 2) * 64;
    const int wn = (w & 3) * 32;
    const int g  = lane >> 2;
    const int tc = (lane & 3) * 2;
    const int tr  = tid >> 3;
    const int tc4 = (tid & 7) * 4;

    const float* Aptr = A + (size_t)(bm + tr) * K + tc4;
    const float* Wptr = W + (size_t)(bn + tr) * K + tc4;

    float acc[4][4][4];
#pragma unroll
    for (int mi = 0; mi < 4; mi++)
#pragma unroll
        for (int ni = 0; ni < 4; ni++)
#pragma unroll
            for (int c = 0; c < 4; c++) acc[mi][ni][c] = 0.f;

    float4 ra[4], rb[4];
#pragma unroll
    for (int i = 0; i < 4; i++) {
        ra[i] = *(const float4*)(Aptr + (size_t)(i * 32) * K);
        rb[i] = *(const float4*)(Wptr + (size_t)(i * 32) * K);
    }

    for (int k0 = 0; k0 < K; k0 += 32) {
#pragma unroll
        for (int i = 0; i < 4; i++) {
            int row = tr + i * 32;
            float vv[4] = {ra[i].x, ra[i].y, ra[i].z, ra[i].w};
            __nv_bfloat16 h[4], l[4];
#pragma unroll
            for (int j = 0; j < 4; j++) {
                h[j] = __float2bfloat16_rn(vv[j]);
                l[j] = __float2bfloat16_rn(vv[j] - __bfloat162float(h[j]));
            }
            *(uint2*)&sAh[row][tc4] = make_uint2(pack_bf16(h[0], h[1]), pack_bf16(h[2], h[3]));
            *(uint2*)&sAl[row][tc4] = make_uint2(pack_bf16(l[0], l[1]), pack_bf16(l[2], l[3]));

            float wv[4] = {rb[i].x, rb[i].y, rb[i].z, rb[i].w};
#pragma unroll
            for (int j = 0; j < 4; j++) {
                h[j] = __float2bfloat16_rn(wv[j]);
                l[j] = __float2bfloat16_rn(wv[j] - __bfloat162float(h[j]));
            }
            *(uint2*)&sBh[row][tc4] = make_uint2(pack_bf16(h[0], h[1]), pack_bf16(h[2], h[3]));
            *(uint2*)&sBl[row][tc4] = make_uint2(pack_bf16(l[0], l[1]), pack_bf16(l[2], l[3]));
        }
        __syncthreads();

        if (k0 + 32 < K) {
#pragma unroll
            for (int i = 0; i < 4; i++) {
                ra[i] = *(const float4*)(Aptr + k0 + 32 + (size_t)(i * 32) * K);
                rb[i] = *(const float4*)(Wptr + k0 + 32 + (size_t)(i * 32) * K);
            }
        }

#pragma unroll
        for (int ks = 0; ks < 32; ks += 16) {
            unsigned ah[4][4], al[4][4], bh[4][2], bl[4][2];
#pragma unroll
            for (int mi = 0; mi < 4; mi++) {
                int r = wm + mi * 16;
                ah[mi][0] = *(const unsigned*)&sAh[r + g    ][ks + tc    ];
                ah[mi][1] = *(const unsigned*)&sAh[r + g + 8][ks + tc    ];
                ah[mi][2] = *(const unsigned*)&sAh[r + g    ][ks + tc + 8];
                ah[mi][3] = *(const unsigned*)&sAh[r + g + 8][ks + tc + 8];
                al[mi][0] = *(const unsigned*)&sAl[r + g    ][ks + tc    ];
                al[mi][1] = *(const unsigned*)&sAl[r + g + 8][ks + tc    ];
                al[mi][2] = *(const unsigned*)&sAl[r + g    ][ks + tc + 8];
                al[mi][3] = *(const unsigned*)&sAl[r + g + 8][ks + tc + 8];
            }
#pragma unroll
            for (int ni = 0; ni < 4; ni++) {
                int n = wn + ni * 8 + g;
                bh[ni][0] = *(const unsigned*)&sBh[n][ks + tc    ];
                bh[ni][1] = *(const unsigned*)&sBh[n][ks + tc + 8];
                bl[ni][0] = *(const unsigned*)&sBl[n][ks + tc    ];
                bl[ni][1] = *(const unsigned*)&sBl[n][ks + tc + 8];
            }
#pragma unroll
            for (int mi = 0; mi < 4; mi++)
#pragma unroll
                for (int ni = 0; ni < 4; ni++) {
                    MMA_BF16(acc[mi][ni], ah[mi], bh[ni]);
                    MMA_BF16(acc[mi][ni], al[mi], bh[ni]);
                    MMA_BF16(acc[mi][ni], ah[mi], bl[ni]);
                }
        }
        __syncthreads();
    }

#pragma unroll
    for (int mi = 0; mi < 4; mi++) {
        int r0 = bm + wm + mi * 16 + g;
#pragma unroll
        for (int ni = 0; ni < 4; ni++) {
            int c0 = bn + wn + ni * 8 + tc;
            float2 bb = *(const float2*)&bias[c0];
            float2 o0 = make_float2(acc[mi][ni][0] + bb.x, acc[mi][ni][1] + bb.y);
            float2 o1 = make_float2(acc[mi][ni][2] + bb.x, acc[mi][ni][3] + bb.y);
            *(float2*)(C + (size_t)r0 * N + c0)       = o0;
            *(float2*)(C + (size_t)(r0 + 8) * N + c0) = o1;
        }
    }
}

// ============================================================================
// GEMM variant: writes hi/lo split bf16 planes (for Q/K/V), scale applied
// before split. Body identical to sgemm_bf16x3; only the epilogue differs.
// ============================================================================
__global__ __launch_bounds__(256) void sgemm_qkv_split(
    const float* __restrict__ A, const float* __restrict__ W,
    const float* __restrict__ bias,
    __nv_bfloat16* __restrict__ OH, __nv_bfloat16* __restrict__ OL,
    float scale, int M, int N, int K)
{
    __shared__ __nv_bfloat16 sAh[128][SSTR];
    __shared__ __nv_bfloat16 sAl[128][SSTR];
    __shared__ __nv_bfloat16 sBh[128][SSTR];
    __shared__ __nv_bfloat16 sBl[128][SSTR];

    const int bm = blockIdx.y * 128;
    const int bn = blockIdx.x * 128;
    const int tid = threadIdx.x;
    const int lane = tid & 31;
    const int w = tid >> 5;
    const int wm = (w >> 2) * 64;
    const int wn = (w & 3) * 32;
    const int g  = lane >> 2;
    const int tc = (lane & 3) * 2;
    const int tr  = tid >> 3;
    const int tc4 = (tid & 7) * 4;

    const float* Aptr = A + (size_t)(bm + tr) * K + tc4;
    const float* Wptr = W + (size_t)(bn + tr) * K + tc4;

    float acc[4][4][4];
#pragma unroll
    for (int mi = 0; mi < 4; mi++)
#pragma unroll
        for (int ni = 0; ni < 4; ni++)
#pragma unroll
            for (int c = 0; c < 4; c++) acc[mi][ni][c] = 0.f;

    float4 ra[4], rb[4];
#pragma unroll
    for (int i = 0; i < 4; i++) {
        ra[i] = *(const float4*)(Aptr + (size_t)(i * 32) * K);
        rb[i] = *(const float4*)(Wptr + (size_t)(i * 32) * K);
    }

    for (int k0 = 0; k0 < K; k0 += 32) {
#pragma unroll
        for (int i = 0; i < 4; i++) {
            int row = tr + i * 32;
            float vv[4] = {ra[i].x, ra[i].y, ra[i].z, ra[i].w};
            __nv_bfloat16 h[4], l[4];
#pragma unroll
            for (int j = 0; j < 4; j++) {
                h[j] = __float2bfloat16_rn(vv[j]);
                l[j] = __float2bfloat16_rn(vv[j] - __bfloat162float(h[j]));
            }
            *(uint2*)&sAh[row][tc4] = make_uint2(pack_bf16(h[0], h[1]), pack_bf16(h[2], h[3]));
            *(uint2*)&sAl[row][tc4] = make_uint2(pack_bf16(l[0], l[1]), pack_bf16(l[2], l[3]));

            float wv[4] = {rb[i].x, rb[i].y, rb[i].z, rb[i].w};
#pragma unroll
            for (int j = 0; j < 4; j++) {
                h[j] = __float2bfloat16_rn(wv[j]);
                l[j] = __float2bfloat16_rn(wv[j] - __bfloat162float(h[j]));
            }
            *(uint2*)&sBh[row][tc4] = make_uint2(pack_bf16(h[0], h[1]), pack_bf16(h[2], h[3]));
            *(uint2*)&sBl[row][tc4] = make_uint2(pack_bf16(l[0], l[1]), pack_bf16(l[2], l[3]));
        }
        __syncthreads();

        if (k0 + 32 < K) {
#pragma unroll
            for (int i = 0; i < 4; i++) {
                ra[i] = *(const float4*)(Aptr + k0 + 32 + (size_t)(i * 32) * K);
                rb[i] = *(const float4*)(Wptr + k0 + 32 + (size_t)(i * 32) * K);
            }
        }

#pragma unroll
        for (int ks = 0; ks < 32; ks += 16) {
            unsigned ah[4][4], al[4][4], bh[4][2], bl[4][2];
#pragma unroll
            for (int mi = 0; mi < 4; mi++) {
                int r = wm + mi * 16;
                ah[mi][0] = *(const unsigned*)&sAh[r + g    ][ks + tc    ];
                ah[mi][1] = *(const unsigned*)&sAh[r + g + 8][ks + tc    ];
                ah[mi][2] = *(const unsigned*)&sAh[r + g    ][ks + tc + 8];
                ah[mi][3] = *(const unsigned*)&sAh[r + g + 8][ks + tc + 8];
                al[mi][0] = *(const unsigned*)&sAl[r + g    ][ks + tc    ];
                al[mi][1] = *(const unsigned*)&sAl[r + g + 8][ks + tc    ];
                al[mi][2] = *(const unsigned*)&sAl[r + g    ][ks + tc + 8];
                al[mi][3] = *(const unsigned*)&sAl[r + g + 8][ks + tc + 8];
            }
#pragma unroll
            for (int ni = 0; ni < 4; ni++) {
                int n = wn + ni * 8 + g;
                bh[ni][0] = *(const unsigned*)&sBh[n][ks + tc    ];
                bh[ni][1] = *(const unsigned*)&sBh[n][ks + tc + 8];
                bl[ni][0] = *(const unsigned*)&sBl[n][ks + tc    ];
                bl[ni][1] = *(const unsigned*)&sBl[n][ks + tc + 8];
            }
#pragma unroll
            for (int mi = 0; mi < 4; mi++)
#pragma unroll
                for (int ni = 0; ni < 4; ni++) {
                    MMA_BF16(acc[mi][ni], ah[mi], bh[ni]);
                    MMA_BF16(acc[mi][ni], al[mi], bh[ni]);
                    MMA_BF16(acc[mi][ni], ah[mi], bl[ni]);
                }
        }
        __syncthreads();
    }

    // ---- epilogue: bias, scale, hi/lo split, store bf16 planes ----
#pragma unroll
    for (int mi = 0; mi < 4; mi++) {
        int r0 = bm + wm + mi * 16 + g;
#pragma unroll
        for (int ni = 0; ni < 4; ni++) {
            int c0 = bn + wn + ni * 8 + tc;
            float2 bb = *(const float2*)&bias[c0];
            float s0 = (acc[mi][ni][0] + bb.x) * scale;
            float s1 = (acc[mi][ni][1] + bb.y) * scale;
            float s2 = (acc[mi][ni][2] + bb.x) * scale;
            float s3 = (acc[mi][ni][3] + bb.y) * scale;
            __nv_bfloat16 h0 = __float2bfloat16_rn(s0);
            __nv_bfloat16 h1 = __float2bfloat16_rn(s1);
            __nv_bfloat16 h2 = __float2bfloat16_rn(s2);
            __nv_bfloat16 h3 = __float2bfloat16_rn(s3);
            __nv_bfloat16 l0 = __float2bfloat16_rn(s0 - __bfloat162float(h0));
            __nv_bfloat16 l1 = __float2bfloat16_rn(s1 - __bfloat162float(h1));
            __nv_bfloat16 l2 = __float2bfloat16_rn(s2 - __bfloat162float(h2));
            __nv_bfloat16 l3 = __float2bfloat16_rn(s3 - __bfloat162float(h3));
            *(unsigned*)&OH[(size_t)r0 * N + c0]       = pack_bf16(h0, h1);
            *(unsigned*)&OH[(size_t)(r0 + 8) * N + c0] = pack_bf16(h2, h3);
            *(unsigned*)&OL[(size_t)r0 * N + c0]       = pack_bf16(l0, l1);
            *(unsigned*)&OL[(size_t)(r0 + 8) * N + c0] = pack_bf16(l2, l3);
        }
    }
}

// ---------------- small projections (unchanged) ----------------
__global__ __launch_bounds__(256) void proj_small(
    const float* __restrict__ x,
    const float* __restrict__ relW, const float* __restrict__ relb,
    const float* __restrict__ gW,   const float* __restrict__ gb)
{
    __shared__ float xs[DIM];
    const int m = blockIdx.x;
    const float* xrow = x + (size_t)m * DIM;
    for (int i = threadIdx.x; i < DIM; i += 256) xs[i] = xrow[i];
    __syncthreads();

    const int warp = threadIdx.x >> 5;
    const int lane = threadIdx.x & 31;
    for (int o = warp; o < 22; o += 8) {
        const float* wp;
        if (o < 3)       wp = relW + (size_t)o * (2*DIM);
        else if (o < 6)  wp = relW + (size_t)(o-3) * (2*DIM) + DIM;
        else             wp = gW   + (size_t)(o-6) * DIM;
        float s = 0.f;
        for (int k = lane; k < DIM; k += 32) s += xs[k] * wp[k];
#pragma unroll
        for (int off = 16; off; off >>= 1) s += __shfl_xor_sync(0xffffffffu, s, off);
        if (lane == 0) {
            if (o < 3)      g_ei[(size_t)m*3 + o]      = expf(s + relb[o]);
            else if (o < 6) g_ej[(size_t)m*3 + (o-3)]  = expf(s);
            else            g_gate[(size_t)m*HEADS + (o-6)] =
                                1.f / (1.f + expf(-(s + gb[o-6])));
        }
    }
}

// ============================================================================
// Fused flash-attention: fills are now pure uint4 copies of pre-split planes.
// ============================================================================
#define BSTR 72
#define ATTN_SMEM ((2*128*BSTR + 2*64*BSTR + 2*64*BSTR)*2 + 192*4)

__global__ __launch_bounds__(256, 1) void attn_mma(const float* __restrict__ lb)
{
    extern __shared__ __nv_bfloat16 smb[];
    __nv_bfloat16* Qh = smb;
    __nv_bfloat16* Ql = Qh + 128*BSTR;
    __nv_bfloat16* Kh = Ql + 128*BSTR;
    __nv_bfloat16* Kl = Kh + 64*BSTR;
    __nv_bfloat16* Vh = Kl + 64*BSTR;
    __nv_bfloat16* Vl = Vh + 64*BSTR;
    float* Ejs = (float*)(Vl + 64*BSTR);

    const int bb = blockIdx.z;
    const int hh = blockIdx.y;
    const int i0 = blockIdx.x * 128;
    const int tid  = threadIdx.x;
    const int lane = tid & 31;
    const int w    = tid >> 5;
    const int wm = w * 16;
    const int g  = lane >> 2;
    const int tc = (lane & 3) * 2;
    const int r0 = wm + g;
    const int r1 = wm + g + 8;

    // ---- Q tile fill: pure copies (pre-scaled, pre-split) ----
    const size_t qoff = ((size_t)(bb*SEQ + i0))*DIM + hh*HD;
    for (int t = tid; t < 128*8; t += 256) {
        int i = t >> 3;
        int k8 = (t & 7) * 8;
        *(uint4*)&Qh[i*BSTR + k8] = *(const uint4*)&g_qh[qoff + (size_t)i*DIM + k8];
        *(uint4*)&Ql[i*BSTR + k8] = *(const uint4*)&g_ql[qoff + (size_t)i*DIM + k8];
    }

    // ---- per-thread relational constants for rows r0, r1 ----
    const float lb0 = lb[hh*3+0];
    const float lb1 = lb[hh*3+1];
    const float lb2 = lb[hh*3+2];
    float fi0[3], ei0[3], fi1[3], ei1[3];
    {
        int gi0 = bb*SEQ + i0 + r0;
        int gi1 = bb*SEQ + i0 + r1;
        float gg0 = g_gate[(size_t)gi0*HEADS + hh];
        float gg1 = g_gate[(size_t)gi1*HEADS + hh];
#pragma unroll
        for (int kk = 0; kk < 3; kk++) {
            ei0[kk] = g_ei[(size_t)gi0*3 + kk];
            ei1[kk] = g_ei[(size_t)gi1*3 + kk];
        }
        fi0[0] = gg0*ei0[0]*lb0; fi0[1] = gg0*ei0[1]*lb1; fi0[2] = gg0*ei0[2]*lb2;
        fi1[0] = gg1*ei1[0]*lb0; fi1[1] = gg1*ei1[1]*lb1; fi1[2] = gg1*ei1[2]*lb2;
    }
    __syncthreads();

    // ---- Q a-fragments (j-invariant) ----
    unsigned qah[4][4], qal[4][4];
#pragma unroll
    for (int ks = 0; ks < 4; ks++) {
        int k0 = ks * 16;
        qah[ks][0] = *(const unsigned*)&Qh[r0*BSTR + k0 + tc    ];
        qah[ks][1] = *(const unsigned*)&Qh[r1*BSTR + k0 + tc    ];
        qah[ks][2] = *(const unsigned*)&Qh[r0*BSTR + k0 + tc + 8];
        qah[ks][3] = *(const unsigned*)&Qh[r1*BSTR + k0 + tc + 8];
        qal[ks][0] = *(const unsigned*)&Ql[r0*BSTR + k0 + tc    ];
        qal[ks][1] = *(const unsigned*)&Ql[r1*BSTR + k0 + tc    ];
        qal[ks][2] = *(const unsigned*)&Ql[r0*BSTR + k0 + tc + 8];
        qal[ks][3] = *(const unsigned*)&Ql[r1*BSTR + k0 + tc + 8];
    }

    // ---- ldmatrix per-lane base offsets (bytes) ----
    const int l7  = lane & 7;
    const int lb3 = (lane >> 3) & 1;
    const int lb4 = (lane >> 4) & 1;
    const unsigned krow_off = (unsigned)(((l7 + lb4*8) * BSTR + lb3*8) * 2);
    const unsigned vrow_off = (unsigned)(((l7 + lb3*8) * BSTR + lb4*8) * 2);
    const unsigned Khb = SMADDR(Kh);
    const unsigned Klb = SMADDR(Kl);
    const unsigned Vhb = SMADDR(Vh);
    const unsigned Vlb = SMADDR(Vl);

    float acc[8][4];
#pragma unroll
    for (int ni = 0; ni < 8; ni++)
#pragma unroll
        for (int c = 0; c < 4; c++) acc[ni][c] = 0.f;
    float m0 = -1e30f, m1 = -1e30f;
    float l0 = 0.f, l1 = 0.f;

    const size_t kvoff = ((size_t)(bb*SEQ))*DIM + hh*HD;

    for (int jt = 0; jt < SEQ/64; jt++) {
        const int j0 = jt * 64;
        __syncthreads();   // prev-iter K/V readers done before overwrite

        // ---- K/V fills: pure uint4 copies of pre-split planes ----
        for (int t = tid; t < 64*8; t += 256) {
            int j = t >> 3;
            int k8 = (t & 7) * 8;
            size_t go = kvoff + (size_t)(j0 + j)*DIM + k8;
            int so = j*BSTR + k8;
            *(uint4*)&Kh[so] = *(const uint4*)&g_kh[go];
            *(uint4*)&Kl[so] = *(const uint4*)&g_kl[go];
            *(uint4*)&Vh[so] = *(const uint4*)&g_vh[go];
            *(uint4*)&Vl[so] = *(const uint4*)&g_vl[go];
        }
        for (int t = tid; t < 64*3; t += 256) {
            Ejs[t] = g_ej[((size_t)(bb*SEQ + j0))*3 + t];
        }
        __syncthreads();

        // ---- S = Q K^T : K b-frags via ldmatrix.x4 ----
        float sc[8][4];
#pragma unroll
        for (int ni = 0; ni < 8; ni++)
#pragma unroll
            for (int c = 0; c < 4; c++) sc[ni][c] = 0.f;
#pragma unroll
        for (int ks = 0; ks < 4; ks++) {
#pragma unroll
            for (int np = 0; np < 4; np++) {
                unsigned kaddr = krow_off + (unsigned)(np*(16*BSTR*2) + ks*32);
                unsigned t0, t1, t2, t3, u0, u1, u2, u3;
                LDMX4(t0, t1, t2, t3, Khb + kaddr);
                LDMX4(u0, u1, u2, u3, Klb + kaddr);
                unsigned bh0[2] = {t0, t1};
                unsigned bh1[2] = {t2, t3};
                unsigned bl0[2] = {u0, u1};
                unsigned bl1[2] = {u2, u3};
                MMA_BF16(sc[2*np    ], qah[ks], bh0);
                MMA_BF16(sc[2*np    ], qal[ks], bh0);
                MMA_BF16(sc[2*np    ], qah[ks], bl0);
                MMA_BF16(sc[2*np + 1], qah[ks], bh1);
                MMA_BF16(sc[2*np + 1], qal[ks], bh1);
                MMA_BF16(sc[2*np + 1], qah[ks], bl1);
            }
        }

        // ---- relational bias (register-resident) ----
#pragma unroll
        for (int ni = 0; ni < 8; ni++) {
            int j = ni*8 + tc;
            float ea0 = Ejs[j*3+0], ea1 = Ejs[j*3+1], ea2 = Ejs[j*3+2];
            float eb0 = Ejs[j*3+3], eb1 = Ejs[j*3+4], eb2 = Ejs[j*3+5];
            sc[ni][0] += __fdividef(fi0[0]*ea0 + fi0[1]*ea1 + fi0[2]*ea2,
                                    ei0[0]*ea0 + ei0[1]*ea1 + ei0[2]*ea2);
            sc[ni][1] += __fdividef(fi0[0]*eb0 + fi0[1]*eb1 + fi0[2]*eb2,
                                    ei0[0]*eb0 + ei0[1]*eb1 + ei0[2]*eb2);
            sc[ni][2] += __fdividef(fi1[0]*ea0 + fi1[1]*ea1 + fi1[2]*ea2,
                                    ei1[0]*ea0 + ei1[1]*ea1 + ei1[2]*ea2);
            sc[ni][3] += __fdividef(fi1[0]*eb0 + fi1[1]*eb1 + fi1[2]*eb2,
                                    ei1[0]*eb0 + ei1[1]*eb1 + ei1[2]*eb2);
        }

        // ---- warp-local online softmax (quad reductions) ----
        float mx0 = -1e30f, mx1 = -1e30f;
#pragma unroll
        for (int ni = 0; ni < 8; ni++) {
            mx0 = fmaxf(mx0, fmaxf(sc[ni][0], sc[ni][1]));
            mx1 = fmaxf(mx1, fmaxf(sc[ni][2], sc[ni][3]));
        }
        mx0 = fmaxf(mx0, __shfl_xor_sync(0xffffffffu, mx0, 1));
        mx0 = fmaxf(mx0, __shfl_xor_sync(0xffffffffu, mx0, 2));
        mx1 = fmaxf(mx1, __shfl_xor_sync(0xffffffffu, mx1, 1));
        mx1 = fmaxf(mx1, __shfl_xor_sync(0xffffffffu, mx1, 2));
        float mn0 = fmaxf(m0, mx0);
        float mn1 = fmaxf(m1, mx1);
        float corr0 = __expf(m0 - mn0);
        float corr1 = __expf(m1 - mn1);

        float rs0 = 0.f, rs1 = 0.f;
        unsigned ph[8][2], pl[8][2];
#pragma unroll
        for (int ni = 0; ni < 8; ni++) {
            float p0 = __expf(sc[ni][0] - mn0);
            float p1 = __expf(sc[ni][1] - mn0);
            float p2 = __expf(sc[ni][2] - mn1);
            float p3 = __expf(sc[ni][3] - mn1);
            rs0 += p0 + p1;
            rs1 += p2 + p3;
            __nv_bfloat16 h0 = __float2bfloat16_rn(p0);
            __nv_bfloat16 h1 = __float2bfloat16_rn(p1);
            __nv_bfloat16 h2 = __float2bfloat16_rn(p2);
            __nv_bfloat16 h3 = __float2bfloat16_rn(p3);
            ph[ni][0] = pack_bf16(h0, h1);
            ph[ni][1] = pack_bf16(h2, h3);
            pl[ni][0] = pack_bf16(__float2bfloat16_rn(p0 - __bfloat162float(h0)),
                                  __float2bfloat16_rn(p1 - __bfloat162float(h1)));
            pl[ni][1] = pack_bf16(__float2bfloat16_rn(p2 - __bfloat162float(h2)),
                                  __float2bfloat16_rn(p3 - __bfloat162float(h3)));
        }
        rs0 += __shfl_xor_sync(0xffffffffu, rs0, 1);
        rs0 += __shfl_xor_sync(0xffffffffu, rs0, 2);
        rs1 += __shfl_xor_sync(0xffffffffu, rs1, 1);
        rs1 += __shfl_xor_sync(0xffffffffu, rs1, 2);
        l0 = l0*corr0 + rs0;
        l1 = l1*corr1 + rs1;
        m0 = mn0;
        m1 = mn1;

        // ---- O = O*corr + P V : V b-frags via ldmatrix.x4.trans ----
#pragma unroll
        for (int ni = 0; ni < 8; ni++) {
            acc[ni][0] *= corr0; acc[ni][1] *= corr0;
            acc[ni][2] *= corr1; acc[ni][3] *= corr1;
        }
#pragma unroll
        for (int ks = 0; ks < 4; ks++) {
            unsigned pah[4], pal[4];
            pah[0] = ph[2*ks  ][0];
            pah[1] = ph[2*ks  ][1];
            pah[2] = ph[2*ks+1][0];
            pah[3] = ph[2*ks+1][1];
            pal[0] = pl[2*ks  ][0];
            pal[1] = pl[2*ks  ][1];
            pal[2] = pl[2*ks+1][0];
            pal[3] = pl[2*ks+1][1];
#pragma unroll
            for (int np = 0; np < 4; np++) {
                unsigned vaddr = vrow_off + (unsigned)(ks*(16*BSTR*2) + np*32);
                unsigned t0, t1, t2, t3, u0, u1, u2, u3;
                LDMX4T(t0, t1, t2, t3, Vhb + vaddr);
                LDMX4T(u0, u1, u2, u3, Vlb + vaddr);
                unsigned vh0[2] = {t0, t1};
                unsigned vh1[2] = {t2, t3};
                unsigned vl0[2] = {u0, u1};
                unsigned vl1[2] = {u2, u3};
                MMA_BF16(acc[2*np    ], pah, vh0);
                MMA_BF16(acc[2*np    ], pal, vh0);
                MMA_BF16(acc[2*np    ], pah, vl0);
                MMA_BF16(acc[2*np + 1], pah, vh1);
                MMA_BF16(acc[2*np + 1], pal, vh1);
                MMA_BF16(acc[2*np + 1], pah, vl1);
            }
        }
    }

    // ---- epilogue: per-thread normalize, store ----
    float inv0 = __frcp_rn(l0);
    float inv1 = __frcp_rn(l1);
    size_t gr0 = (size_t)(bb*SEQ + i0 + r0);
    size_t gr1 = (size_t)(bb*SEQ + i0 + r1);
#pragma unroll
    for (int ni = 0; ni < 8; ni++) {
        int col = hh*HD + ni*8 + tc;
        *(float2*)(g_ctx + gr0*DIM + col) =
            make_float2(acc[ni][0]*inv0, acc[ni][1]*inv0);
        *(float2*)(g_ctx + gr1*DIM + col) =
            make_float2(acc[ni][2]*inv1, acc[ni][3]*inv1);
    }
}

// ---------------- launcher ----------------
extern "C" void kernel_launch(void* const* d_in, const int* in_sizes, int n_in,
                              void* d_out, int out_size)
{
    (void)in_sizes; (void)n_in; (void)out_size;
    const float* x    = (const float*)d_in[0];
    const float* Wq   = (const float*)d_in[1];
    const float* bq   = (const float*)d_in[2];
    const float* Wk   = (const float*)d_in[3];
    const float* bk   = (const float*)d_in[4];
    const float* Wv   = (const float*)d_in[5];
    const float* bv   = (const float*)d_in[6];
    const float* Wo   = (const float*)d_in[7];
    const float* bo   = (const float*)d_in[8];
    const float* relW = (const float*)d_in[9];
    const float* relb = (const float*)d_in[10];
    const float* lb   = (const float*)d_in[11];
    const float* gW   = (const float*)d_in[12];
    const float* gb   = (const float*)d_in[13];

    __nv_bfloat16 *qh, *ql, *kh, *kl, *vh, *vl;
    float *ctx;
    cudaGetSymbolAddress((void**)&qh,  g_qh);
    cudaGetSymbolAddress((void**)&ql,  g_ql);
    cudaGetSymbolAddress((void**)&kh,  g_kh);
    cudaGetSymbolAddress((void**)&kl,  g_kl);
    cudaGetSymbolAddress((void**)&vh,  g_vh);
    cudaGetSymbolAddress((void**)&vl,  g_vl);
    cudaGetSymbolAddress((void**)&ctx, g_ctx);

    cudaFuncSetAttribute(attn_mma,
                         cudaFuncAttributeMaxDynamicSharedMemorySize, ATTN_SMEM);

    dim3 ggrid(DIM/128, MROWS/128);
    sgemm_qkv_split<<<ggrid, 256>>>(x, Wq, bq, qh, ql, 0.125f, MROWS, DIM, DIM);
    sgemm_qkv_split<<<ggrid, 256>>>(x, Wk, bk, kh, kl, 1.0f,   MROWS, DIM, DIM);
    sgemm_qkv_split<<<ggrid, 256>>>(x, Wv, bv, vh, vl, 1.0f,   MROWS, DIM, DIM);
    proj_small<<<MROWS, 256>>>(x, relW, relb, gW, gb);

    attn_mma<<<dim3(SEQ/128, HEADS, BATCH), 256, ATTN_SMEM>>>(lb);

    sgemm_bf16x3<<<ggrid, 256>>>(ctx, Wo, bo, (float*)d_out, MROWS, DIM, DIM);
}

// round 11
// speedup vs baseline: 2.3027x; 1.0524x over previous
#include <cuda_runtime.h>
#include <cuda_bf16.h>
#include <math.h>

#define BATCH 2
#define SEQ   2048
#define DIM   1024
#define HEADS 16
#define HD    64
#define MROWS (BATCH*SEQ)

// ---------------- scratch (device globals: allocation-free) ----------------
__device__ __nv_bfloat16 g_qh[MROWS*DIM];
__device__ __nv_bfloat16 g_ql[MROWS*DIM];
__device__ __nv_bfloat16 g_kh[MROWS*DIM];
__device__ __nv_bfloat16 g_kl[MROWS*DIM];
__device__ __nv_bfloat16 g_vh[MROWS*DIM];
__device__ __nv_bfloat16 g_vl[MROWS*DIM];
__device__ float g_ctx[MROWS*DIM];
__device__ float g_ei[MROWS*3];
__device__ float g_ej[MROWS*3];
__device__ float g_gate[MROWS*HEADS];

// ---------------- helpers ----------------
__device__ __forceinline__ unsigned pack_bf16(__nv_bfloat16 a, __nv_bfloat16 b) {
    return (unsigned)__bfloat16_as_ushort(a) | ((unsigned)__bfloat16_as_ushort(b) << 16);
}

#define SMADDR(p) ((unsigned)__cvta_generic_to_shared(p))

#define MMA_BF16(c, a, b) \
    asm volatile("mma.sync.aligned.m16n8k16.row.col.f32.bf16.bf16.f32 " \
                 "{%0,%1,%2,%3}, {%4,%5,%6,%7}, {%8,%9}, {%0,%1,%2,%3};" \
                 : "+f"(c[0]), "+f"(c[1]), "+f"(c[2]), "+f"(c[3]) \
                 : "r"(a[0]), "r"(a[1]), "r"(a[2]), "r"(a[3]), "r"(b[0]), "r"(b[1]))

#define LDMX4(r0, r1, r2, r3, addr) \
    asm volatile("ldmatrix.sync.aligned.m8n8.x4.shared.b16 {%0,%1,%2,%3}, [%4];" \
                 : "=r"(r0), "=r"(r1), "=r"(r2), "=r"(r3) : "r"(addr))

#define LDMX4T(r0, r1, r2, r3, addr) \
    asm volatile("ldmatrix.sync.aligned.m8n8.x4.trans.shared.b16 {%0,%1,%2,%3}, [%4];" \
                 : "=r"(r0), "=r"(r1), "=r"(r2), "=r"(r3) : "r"(addr))

// ============================================================================
// GEMM (2-stage pipelined): C = A @ W^T + bias, fp32 out (used for Wo)
// Dynamic smem: 2 stages x 4 planes x 128 x SSTR bf16 = 81920 B
// ============================================================================
#define SSTR 40
#define GTILE (128*SSTR)
#define GSM_BYTES (2*4*GTILE*2)

__global__ __launch_bounds__(256) void sgemm_bf16x3(
    const float* __restrict__ A, const float* __restrict__ W,
    const float* __restrict__ bias, float* __restrict__ C,
    int M, int N, int K)
{
    extern __shared__ __nv_bfloat16 smb[];

    const int bm = blockIdx.y * 128;
    const int bn = blockIdx.x * 128;
    const int tid = threadIdx.x;
    const int lane = tid & 31;
    const int w = tid >> 5;
    const int wm = (w >> 2) * 64;
    const int wn = (w & 3) * 32;
    const int g  = lane >> 2;
    const int tc = (lane & 3) * 2;
    const int tr  = tid >> 3;
    const int tc4 = (tid & 7) * 4;

    const float* Aptr = A + (size_t)(bm + tr) * K + tc4;
    const float* Wptr = W + (size_t)(bn + tr) * K + tc4;

    float acc[4][4][4];
#pragma unroll
    for (int mi = 0; mi < 4; mi++)
#pragma unroll
        for (int ni = 0; ni < 4; ni++)
#pragma unroll
            for (int c = 0; c < 4; c++) acc[mi][ni][c] = 0.f;

    float4 ra[4], rb[4];
#pragma unroll
    for (int i = 0; i < 4; i++) {
        ra[i] = *(const float4*)(Aptr + (size_t)(i * 32) * K);
        rb[i] = *(const float4*)(Wptr + (size_t)(i * 32) * K);
    }

    // ---- prologue: convert-store slab 0 into stage 0 ----
    {
        __nv_bfloat16* sAh = smb + 0*GTILE;
        __nv_bfloat16* sAl = smb + 1*GTILE;
        __nv_bfloat16* sBh = smb + 2*GTILE;
        __nv_bfloat16* sBl = smb + 3*GTILE;
#pragma unroll
        for (int i = 0; i < 4; i++) {
            int row = tr + i * 32;
            float vv[4] = {ra[i].x, ra[i].y, ra[i].z, ra[i].w};
            __nv_bfloat16 h[4], l[4];
#pragma unroll
            for (int j = 0; j < 4; j++) {
                h[j] = __float2bfloat16_rn(vv[j]);
                l[j] = __float2bfloat16_rn(vv[j] - __bfloat162float(h[j]));
            }
            *(uint2*)&sAh[row*SSTR + tc4] = make_uint2(pack_bf16(h[0], h[1]), pack_bf16(h[2], h[3]));
            *(uint2*)&sAl[row*SSTR + tc4] = make_uint2(pack_bf16(l[0], l[1]), pack_bf16(l[2], l[3]));
            float wv[4] = {rb[i].x, rb[i].y, rb[i].z, rb[i].w};
#pragma unroll
            for (int j = 0; j < 4; j++) {
                h[j] = __float2bfloat16_rn(wv[j]);
                l[j] = __float2bfloat16_rn(wv[j] - __bfloat162float(h[j]));
            }
            *(uint2*)&sBh[row*SSTR + tc4] = make_uint2(pack_bf16(h[0], h[1]), pack_bf16(h[2], h[3]));
            *(uint2*)&sBl[row*SSTR + tc4] = make_uint2(pack_bf16(l[0], l[1]), pack_bf16(l[2], l[3]));
        }
    }
    __syncthreads();

    for (int k0 = 0; k0 < K; k0 += 32) {
        const int cur = (k0 >> 5) & 1;
        const int nxt = cur ^ 1;
        const bool has_next = (k0 + 32 < K);

        if (has_next) {
#pragma unroll
            for (int i = 0; i < 4; i++) {
                ra[i] = *(const float4*)(Aptr + k0 + 32 + (size_t)(i * 32) * K);
                rb[i] = *(const float4*)(Wptr + k0 + 32 + (size_t)(i * 32) * K);
            }
        }

        const __nv_bfloat16* cAh = smb + (cur*4 + 0)*GTILE;
        const __nv_bfloat16* cAl = smb + (cur*4 + 1)*GTILE;
        const __nv_bfloat16* cBh = smb + (cur*4 + 2)*GTILE;
        const __nv_bfloat16* cBl = smb + (cur*4 + 3)*GTILE;

#pragma unroll
        for (int ks = 0; ks < 32; ks += 16) {
            unsigned ah[4][4], al[4][4], bh[4][2], bl[4][2];
#pragma unroll
            for (int mi = 0; mi < 4; mi++) {
                int r = wm + mi * 16;
                ah[mi][0] = *(const unsigned*)&cAh[(r + g    )*SSTR + ks + tc    ];
                ah[mi][1] = *(const unsigned*)&cAh[(r + g + 8)*SSTR + ks + tc    ];
                ah[mi][2] = *(const unsigned*)&cAh[(r + g    )*SSTR + ks + tc + 8];
                ah[mi][3] = *(const unsigned*)&cAh[(r + g + 8)*SSTR + ks + tc + 8];
                al[mi][0] = *(const unsigned*)&cAl[(r + g    )*SSTR + ks + tc    ];
                al[mi][1] = *(const unsigned*)&cAl[(r + g + 8)*SSTR + ks + tc    ];
                al[mi][2] = *(const unsigned*)&cAl[(r + g    )*SSTR + ks + tc + 8];
                al[mi][3] = *(const unsigned*)&cAl[(r + g + 8)*SSTR + ks + tc + 8];
            }
#pragma unroll
            for (int ni = 0; ni < 4; ni++) {
                int n = wn + ni * 8 + g;
                bh[ni][0] = *(const unsigned*)&cBh[n*SSTR + ks + tc    ];
                bh[ni][1] = *(const unsigned*)&cBh[n*SSTR + ks + tc + 8];
                bl[ni][0] = *(const unsigned*)&cBl[n*SSTR + ks + tc    ];
                bl[ni][1] = *(const unsigned*)&cBl[n*SSTR + ks + tc + 8];
            }
#pragma unroll
            for (int mi = 0; mi < 4; mi++)
#pragma unroll
                for (int ni = 0; ni < 4; ni++) {
                    MMA_BF16(acc[mi][ni], ah[mi], bh[ni]);
                    MMA_BF16(acc[mi][ni], al[mi], bh[ni]);
                    MMA_BF16(acc[mi][ni], ah[mi], bl[ni]);
                }
        }

        if (has_next) {
            __nv_bfloat16* nAh = smb + (nxt*4 + 0)*GTILE;
            __nv_bfloat16* nAl = smb + (nxt*4 + 1)*GTILE;
            __nv_bfloat16* nBh = smb + (nxt*4 + 2)*GTILE;
            __nv_bfloat16* nBl = smb + (nxt*4 + 3)*GTILE;
#pragma unroll
            for (int i = 0; i < 4; i++) {
                int row = tr + i * 32;
                float vv[4] = {ra[i].x, ra[i].y, ra[i].z, ra[i].w};
                __nv_bfloat16 h[4], l[4];
#pragma unroll
                for (int j = 0; j < 4; j++) {
                    h[j] = __float2bfloat16_rn(vv[j]);
                    l[j] = __float2bfloat16_rn(vv[j] - __bfloat162float(h[j]));
                }
                *(uint2*)&nAh[row*SSTR + tc4] = make_uint2(pack_bf16(h[0], h[1]), pack_bf16(h[2], h[3]));
                *(uint2*)&nAl[row*SSTR + tc4] = make_uint2(pack_bf16(l[0], l[1]), pack_bf16(l[2], l[3]));
                float wv[4] = {rb[i].x, rb[i].y, rb[i].z, rb[i].w};
#pragma unroll
                for (int j = 0; j < 4; j++) {
                    h[j] = __float2bfloat16_rn(wv[j]);
                    l[j] = __float2bfloat16_rn(wv[j] - __bfloat162float(h[j]));
                }
                *(uint2*)&nBh[row*SSTR + tc4] = make_uint2(pack_bf16(h[0], h[1]), pack_bf16(h[2], h[3]));
                *(uint2*)&nBl[row*SSTR + tc4] = make_uint2(pack_bf16(l[0], l[1]), pack_bf16(l[2], l[3]));
            }
        }
        __syncthreads();
    }

#pragma unroll
    for (int mi = 0; mi < 4; mi++) {
        int r0 = bm + wm + mi * 16 + g;
#pragma unroll
        for (int ni = 0; ni < 4; ni++) {
            int c0 = bn + wn + ni * 8 + tc;
            float2 bb = *(const float2*)&bias[c0];
            float2 o0 = make_float2(acc[mi][ni][0] + bb.x, acc[mi][ni][1] + bb.y);
            float2 o1 = make_float2(acc[mi][ni][2] + bb.x, acc[mi][ni][3] + bb.y);
            *(float2*)(C + (size_t)r0 * N + c0)       = o0;
            *(float2*)(C + (size_t)(r0 + 8) * N + c0) = o1;
        }
    }
}

// ============================================================================
// GEMM variant (2-stage pipelined): split hi/lo bf16 output for Q/K/V.
// ============================================================================
__global__ __launch_bounds__(256) void sgemm_qkv_split(
    const float* __restrict__ A, const float* __restrict__ W,
    const float* __restrict__ bias,
    __nv_bfloat16* __restrict__ OH, __nv_bfloat16* __restrict__ OL,
    float scale, int M, int N, int K)
{
    extern __shared__ __nv_bfloat16 smb[];

    const int bm = blockIdx.y * 128;
    const int bn = blockIdx.x * 128;
    const int tid = threadIdx.x;
    const int lane = tid & 31;
    const int w = tid >> 5;
    const int wm = (w >> 2) * 64;
    const int wn = (w & 3) * 32;
    const int g  = lane >> 2;
    const int tc = (lane & 3) * 2;
    const int tr  = tid >> 3;
    const int tc4 = (tid & 7) * 4;

    const float* Aptr = A + (size_t)(bm + tr) * K + tc4;
    const float* Wptr = W + (size_t)(bn + tr) * K + tc4;

    float acc[4][4][4];
#pragma unroll
    for (int mi = 0; mi < 4; mi++)
#pragma unroll
        for (int ni = 0; ni < 4; ni++)
#pragma unroll
            for (int c = 0; c < 4; c++) acc[mi][ni][c] = 0.f;

    float4 ra[4], rb[4];
#pragma unroll
    for (int i = 0; i < 4; i++) {
        ra[i] = *(const float4*)(Aptr + (size_t)(i * 32) * K);
        rb[i] = *(const float4*)(Wptr + (size_t)(i * 32) * K);
    }

    {
        __nv_bfloat16* sAh = smb + 0*GTILE;
        __nv_bfloat16* sAl = smb + 1*GTILE;
        __nv_bfloat16* sBh = smb + 2*GTILE;
        __nv_bfloat16* sBl = smb + 3*GTILE;
#pragma unroll
        for (int i = 0; i < 4; i++) {
            int row = tr + i * 32;
            float vv[4] = {ra[i].x, ra[i].y, ra[i].z, ra[i].w};
            __nv_bfloat16 h[4], l[4];
#pragma unroll
            for (int j = 0; j < 4; j++) {
                h[j] = __float2bfloat16_rn(vv[j]);
                l[j] = __float2bfloat16_rn(vv[j] - __bfloat162float(h[j]));
            }
            *(uint2*)&sAh[row*SSTR + tc4] = make_uint2(pack_bf16(h[0], h[1]), pack_bf16(h[2], h[3]));
            *(uint2*)&sAl[row*SSTR + tc4] = make_uint2(pack_bf16(l[0], l[1]), pack_bf16(l[2], l[3]));
            float wv[4] = {rb[i].x, rb[i].y, rb[i].z, rb[i].w};
#pragma unroll
            for (int j = 0; j < 4; j++) {
                h[j] = __float2bfloat16_rn(wv[j]);
                l[j] = __float2bfloat16_rn(wv[j] - __bfloat162float(h[j]));
            }
            *(uint2*)&sBh[row*SSTR + tc4] = make_uint2(pack_bf16(h[0], h[1]), pack_bf16(h[2], h[3]));
            *(uint2*)&sBl[row*SSTR + tc4] = make_uint2(pack_bf16(l[0], l[1]), pack_bf16(l[2], l[3]));
        }
    }
    __syncthreads();

    for (int k0 = 0; k0 < K; k0 += 32) {
        const int cur = (k0 >> 5) & 1;
        const int nxt = cur ^ 1;
        const bool has_next = (k0 + 32 < K);

        if (has_next) {
#pragma unroll
            for (int i = 0; i < 4; i++) {
                ra[i] = *(const float4*)(Aptr + k0 + 32 + (size_t)(i * 32) * K);
                rb[i] = *(const float4*)(Wptr + k0 + 32 + (size_t)(i * 32) * K);
            }
        }

        const __nv_bfloat16* cAh = smb + (cur*4 + 0)*GTILE;
        const __nv_bfloat16* cAl = smb + (cur*4 + 1)*GTILE;
        const __nv_bfloat16* cBh = smb + (cur*4 + 2)*GTILE;
        const __nv_bfloat16* cBl = smb + (cur*4 + 3)*GTILE;

#pragma unroll
        for (int ks = 0; ks < 32; ks += 16) {
            unsigned ah[4][4], al[4][4], bh[4][2], bl[4][2];
#pragma unroll
            for (int mi = 0; mi < 4; mi++) {
                int r = wm + mi * 16;
                ah[mi][0] = *(const unsigned*)&cAh[(r + g    )*SSTR + ks + tc    ];
                ah[mi][1] = *(const unsigned*)&cAh[(r + g + 8)*SSTR + ks + tc    ];
                ah[mi][2] = *(const unsigned*)&cAh[(r + g    )*SSTR + ks + tc + 8];
                ah[mi][3] = *(const unsigned*)&cAh[(r + g + 8)*SSTR + ks + tc + 8];
                al[mi][0] = *(const unsigned*)&cAl[(r + g    )*SSTR + ks + tc    ];
                al[mi][1] = *(const unsigned*)&cAl[(r + g + 8)*SSTR + ks + tc    ];
                al[mi][2] = *(const unsigned*)&cAl[(r + g    )*SSTR + ks + tc + 8];
                al[mi][3] = *(const unsigned*)&cAl[(r + g + 8)*SSTR + ks + tc + 8];
            }
#pragma unroll
            for (int ni = 0; ni < 4; ni++) {
                int n = wn + ni * 8 + g;
                bh[ni][0] = *(const unsigned*)&cBh[n*SSTR + ks + tc    ];
                bh[ni][1] = *(const unsigned*)&cBh[n*SSTR + ks + tc + 8];
                bl[ni][0] = *(const unsigned*)&cBl[n*SSTR + ks + tc    ];
                bl[ni][1] = *(const unsigned*)&cBl[n*SSTR + ks + tc + 8];
            }
#pragma unroll
            for (int mi = 0; mi < 4; mi++)
#pragma unroll
                for (int ni = 0; ni < 4; ni++) {
                    MMA_BF16(acc[mi][ni], ah[mi], bh[ni]);
                    MMA_BF16(acc[mi][ni], al[mi], bh[ni]);
                    MMA_BF16(acc[mi][ni], ah[mi], bl[ni]);
                }
        }

        if (has_next) {
            __nv_bfloat16* nAh = smb + (nxt*4 + 0)*GTILE;
            __nv_bfloat16* nAl = smb + (nxt*4 + 1)*GTILE;
            __nv_bfloat16* nBh = smb + (nxt*4 + 2)*GTILE;
            __nv_bfloat16* nBl = smb + (nxt*4 + 3)*GTILE;
#pragma unroll
            for (int i = 0; i < 4; i++) {
                int row = tr + i * 32;
                float vv[4] = {ra[i].x, ra[i].y, ra[i].z, ra[i].w};
                __nv_bfloat16 h[4], l[4];
#pragma unroll
                for (int j = 0; j < 4; j++) {
                    h[j] = __float2bfloat16_rn(vv[j]);
                    l[j] = __float2bfloat16_rn(vv[j] - __bfloat162float(h[j]));
                }
                *(uint2*)&nAh[row*SSTR + tc4] = make_uint2(pack_bf16(h[0], h[1]), pack_bf16(h[2], h[3]));
                *(uint2*)&nAl[row*SSTR + tc4] = make_uint2(pack_bf16(l[0], l[1]), pack_bf16(l[2], l[3]));
                float wv[4] = {rb[i].x, rb[i].y, rb[i].z, rb[i].w};
#pragma unroll
                for (int j = 0; j < 4; j++) {
                    h[j] = __float2bfloat16_rn(wv[j]);
                    l[j] = __float2bfloat16_rn(wv[j] - __bfloat162float(h[j]));
                }
                *(uint2*)&nBh[row*SSTR + tc4] = make_uint2(pack_bf16(h[0], h[1]), pack_bf16(h[2], h[3]));
                *(uint2*)&nBl[row*SSTR + tc4] = make_uint2(pack_bf16(l[0], l[1]), pack_bf16(l[2], l[3]));
            }
        }
        __syncthreads();
    }

    // ---- epilogue: bias, scale, hi/lo split, store bf16 planes ----
#pragma unroll
    for (int mi = 0; mi < 4; mi++) {
        int r0 = bm + wm + mi * 16 + g;
#pragma unroll
        for (int ni = 0; ni < 4; ni++) {
            int c0 = bn + wn + ni * 8 + tc;
            float2 bb = *(const float2*)&bias[c0];
            float s0 = (acc[mi][ni][0] + bb.x) * scale;
            float s1 = (acc[mi][ni][1] + bb.y) * scale;
            float s2 = (acc[mi][ni][2] + bb.x) * scale;
            float s3 = (acc[mi][ni][3] + bb.y) * scale;
            __nv_bfloat16 h0 = __float2bfloat16_rn(s0);
            __nv_bfloat16 h1 = __float2bfloat16_rn(s1);
            __nv_bfloat16 h2 = __float2bfloat16_rn(s2);
            __nv_bfloat16 h3 = __float2bfloat16_rn(s3);
            __nv_bfloat16 l0 = __float2bfloat16_rn(s0 - __bfloat162float(h0));
            __nv_bfloat16 l1 = __float2bfloat16_rn(s1 - __bfloat162float(h1));
            __nv_bfloat16 l2 = __float2bfloat16_rn(s2 - __bfloat162float(h2));
            __nv_bfloat16 l3 = __float2bfloat16_rn(s3 - __bfloat162float(h3));
            *(unsigned*)&OH[(size_t)r0 * N + c0]       = pack_bf16(h0, h1);
            *(unsigned*)&OH[(size_t)(r0 + 8) * N + c0] = pack_bf16(h2, h3);
            *(unsigned*)&OL[(size_t)r0 * N + c0]       = pack_bf16(l0, l1);
            *(unsigned*)&OL[(size_t)(r0 + 8) * N + c0] = pack_bf16(l2, l3);
        }
    }
}

// ---------------- small projections (unchanged) ----------------
__global__ __launch_bounds__(256) void proj_small(
    const float* __restrict__ x,
    const float* __restrict__ relW, const float* __restrict__ relb,
    const float* __restrict__ gW,   const float* __restrict__ gb)
{
    __shared__ float xs[DIM];
    const int m = blockIdx.x;
    const float* xrow = x + (size_t)m * DIM;
    for (int i = threadIdx.x; i < DIM; i += 256) xs[i] = xrow[i];
    __syncthreads();

    const int warp = threadIdx.x >> 5;
    const int lane = threadIdx.x & 31;
    for (int o = warp; o < 22; o += 8) {
        const float* wp;
        if (o < 3)       wp = relW + (size_t)o * (2*DIM);
        else if (o < 6)  wp = relW + (size_t)(o-3) * (2*DIM) + DIM;
        else             wp = gW   + (size_t)(o-6) * DIM;
        float s = 0.f;
        for (int k = lane; k < DIM; k += 32) s += xs[k] * wp[k];
#pragma unroll
        for (int off = 16; off; off >>= 1) s += __shfl_xor_sync(0xffffffffu, s, off);
        if (lane == 0) {
            if (o < 3)      g_ei[(size_t)m*3 + o]      = expf(s + relb[o]);
            else if (o < 6) g_ej[(size_t)m*3 + (o-3)]  = expf(s);
            else            g_gate[(size_t)m*HEADS + (o-6)] =
                                1.f / (1.f + expf(-(s + gb[o-6])));
        }
    }
}

// ============================================================================
// Fused flash-attention: 2-stage K/V/Ej double buffering, one sync per j-tile.
// ============================================================================
#define BSTR 72
#define KVBASE (2*128*BSTR)                 // elems before K/V region
#define KVSTAGE (4*64*BSTR)                 // elems per stage (4 planes)
#define ATTN_SMEM ((KVBASE + 2*KVSTAGE)*2 + 2*192*4)

__global__ __launch_bounds__(256, 1) void attn_mma(const float* __restrict__ lb)
{
    extern __shared__ __nv_bfloat16 smb[];
    __nv_bfloat16* Qh = smb;
    __nv_bfloat16* Ql = Qh + 128*BSTR;
    float* ejbase = (float*)(smb + KVBASE + 2*KVSTAGE);

    const int bb = blockIdx.z;
    const int hh = blockIdx.y;
    const int i0 = blockIdx.x * 128;
    const int tid  = threadIdx.x;
    const int lane = tid & 31;
    const int w    = tid >> 5;
    const int wm = w * 16;
    const int g  = lane >> 2;
    const int tc = (lane & 3) * 2;
    const int r0 = wm + g;
    const int r1 = wm + g + 8;

    const size_t kvoff = ((size_t)(bb*SEQ))*DIM + hh*HD;

    // ---- Q tile fill + prologue K/V/Ej fill (stage 0, j0=0) ----
    const size_t qoff = ((size_t)(bb*SEQ + i0))*DIM + hh*HD;
    for (int t = tid; t < 128*8; t += 256) {
        int i = t >> 3;
        int k8 = (t & 7) * 8;
        *(uint4*)&Qh[i*BSTR + k8] = *(const uint4*)&g_qh[qoff + (size_t)i*DIM + k8];
        *(uint4*)&Ql[i*BSTR + k8] = *(const uint4*)&g_ql[qoff + (size_t)i*DIM + k8];
    }
    {
        __nv_bfloat16* sK = smb + KVBASE;   // stage 0
        for (int t = tid; t < 64*8; t += 256) {
            int j = t >> 3;
            int k8 = (t & 7) * 8;
            size_t go = kvoff + (size_t)j*DIM + k8;
            int so = j*BSTR + k8;
            *(uint4*)&sK[so              ] = *(const uint4*)&g_kh[go];
            *(uint4*)&sK[so +   64*BSTR  ] = *(const uint4*)&g_kl[go];
            *(uint4*)&sK[so + 2*64*BSTR  ] = *(const uint4*)&g_vh[go];
            *(uint4*)&sK[so + 3*64*BSTR  ] = *(const uint4*)&g_vl[go];
        }
        for (int t = tid; t < 64*3; t += 256)
            ejbase[t] = g_ej[((size_t)(bb*SEQ))*3 + t];
    }

    // ---- per-thread relational constants ----
    const float lb0 = lb[hh*3+0];
    const float lb1 = lb[hh*3+1];
    const float lb2 = lb[hh*3+2];
    float fi0[3], ei0[3], fi1[3], ei1[3];
    {
        int gi0 = bb*SEQ + i0 + r0;
        int gi1 = bb*SEQ + i0 + r1;
        float gg0 = g_gate[(size_t)gi0*HEADS + hh];
        float gg1 = g_gate[(size_t)gi1*HEADS + hh];
#pragma unroll
        for (int kk = 0; kk < 3; kk++) {
            ei0[kk] = g_ei[(size_t)gi0*3 + kk];
            ei1[kk] = g_ei[(size_t)gi1*3 + kk];
        }
        fi0[0] = gg0*ei0[0]*lb0; fi0[1] = gg0*ei0[1]*lb1; fi0[2] = gg0*ei0[2]*lb2;
        fi1[0] = gg1*ei1[0]*lb0; fi1[1] = gg1*ei1[1]*lb1; fi1[2] = gg1*ei1[2]*lb2;
    }
    __syncthreads();

    // ---- Q a-fragments (j-invariant) ----
    unsigned qah[4][4], qal[4][4];
#pragma unroll
    for (int ks = 0; ks < 4; ks++) {
        int k0 = ks * 16;
        qah[ks][0] = *(const unsigned*)&Qh[r0*BSTR + k0 + tc    ];
        qah[ks][1] = *(const unsigned*)&Qh[r1*BSTR + k0 + tc    ];
        qah[ks][2] = *(const unsigned*)&Qh[r0*BSTR + k0 + tc + 8];
        qah[ks][3] = *(const unsigned*)&Qh[r1*BSTR + k0 + tc + 8];
        qal[ks][0] = *(const unsigned*)&Ql[r0*BSTR + k0 + tc    ];
        qal[ks][1] = *(const unsigned*)&Ql[r1*BSTR + k0 + tc    ];
        qal[ks][2] = *(const unsigned*)&Ql[r0*BSTR + k0 + tc + 8];
        qal[ks][3] = *(const unsigned*)&Ql[r1*BSTR + k0 + tc + 8];
    }

    // ---- ldmatrix per-lane base offsets (bytes) ----
    const int l7  = lane & 7;
    const int lb3 = (lane >> 3) & 1;
    const int lb4 = (lane >> 4) & 1;
    const unsigned krow_off = (unsigned)(((l7 + lb4*8) * BSTR + lb3*8) * 2);
    const unsigned vrow_off = (unsigned)(((l7 + lb3*8) * BSTR + lb4*8) * 2);
    const unsigned KV0 = SMADDR(smb + KVBASE);
    const unsigned STAGEB = (unsigned)(KVSTAGE * 2);      // stage stride bytes
    const unsigned PLANEB = (unsigned)(64*BSTR*2);        // plane stride bytes

    float acc[8][4];
#pragma unroll
    for (int ni = 0; ni < 8; ni++)
#pragma unroll
        for (int c = 0; c < 4; c++) acc[ni][c] = 0.f;
    float m0 = -1e30f, m1 = -1e30f;
    float l0 = 0.f, l1 = 0.f;

    for (int jt = 0; jt < SEQ/64; jt++) {
        const int cur = jt & 1;
        const int nxt = cur ^ 1;

        // ---- fill next stage (overlaps with this tile's MMAs) ----
        if (jt + 1 < SEQ/64) {
            const int j0n = (jt + 1) * 64;
            __nv_bfloat16* sK = smb + KVBASE + nxt*KVSTAGE;
            for (int t = tid; t < 64*8; t += 256) {
                int j = t >> 3;
                int k8 = (t & 7) * 8;
                size_t go = kvoff + (size_t)(j0n + j)*DIM + k8;
                int so = j*BSTR + k8;
                *(uint4*)&sK[so              ] = *(const uint4*)&g_kh[go];
                *(uint4*)&sK[so +   64*BSTR  ] = *(const uint4*)&g_kl[go];
                *(uint4*)&sK[so + 2*64*BSTR  ] = *(const uint4*)&g_vh[go];
                *(uint4*)&sK[so + 3*64*BSTR  ] = *(const uint4*)&g_vl[go];
            }
            float* ejn = ejbase + nxt*192;
            for (int t = tid; t < 64*3; t += 256)
                ejn[t] = g_ej[((size_t)(bb*SEQ + j0n))*3 + t];
        }

        const unsigned Khb = KV0 + (unsigned)cur*STAGEB;
        const unsigned Klb = Khb + PLANEB;
        const unsigned Vhb = Khb + 2*PLANEB;
        const unsigned Vlb = Khb + 3*PLANEB;
        const float* Ejs = ejbase + cur*192;

        // ---- S = Q K^T : K b-frags via ldmatrix.x4 ----
        float sc[8][4];
#pragma unroll
        for (int ni = 0; ni < 8; ni++)
#pragma unroll
            for (int c = 0; c < 4; c++) sc[ni][c] = 0.f;
#pragma unroll
        for (int ks = 0; ks < 4; ks++) {
#pragma unroll
            for (int np = 0; np < 4; np++) {
                unsigned kaddr = krow_off + (unsigned)(np*(16*BSTR*2) + ks*32);
                unsigned t0, t1, t2, t3, u0, u1, u2, u3;
                LDMX4(t0, t1, t2, t3, Khb + kaddr);
                LDMX4(u0, u1, u2, u3, Klb + kaddr);
                unsigned bh0[2] = {t0, t1};
                unsigned bh1[2] = {t2, t3};
                unsigned bl0[2] = {u0, u1};
                unsigned bl1[2] = {u2, u3};
                MMA_BF16(sc[2*np    ], qah[ks], bh0);
                MMA_BF16(sc[2*np    ], qal[ks], bh0);
                MMA_BF16(sc[2*np    ], qah[ks], bl0);
                MMA_BF16(sc[2*np + 1], qah[ks], bh1);
                MMA_BF16(sc[2*np + 1], qal[ks], bh1);
                MMA_BF16(sc[2*np + 1], qah[ks], bl1);
            }
        }

        // ---- relational bias ----
#pragma unroll
        for (int ni = 0; ni < 8; ni++) {
            int j = ni*8 + tc;
            float ea0 = Ejs[j*3+0], ea1 = Ejs[j*3+1], ea2 = Ejs[j*3+2];
            float eb0 = Ejs[j*3+3], eb1 = Ejs[j*3+4], eb2 = Ejs[j*3+5];
            sc[ni][0] += __fdividef(fi0[0]*ea0 + fi0[1]*ea1 + fi0[2]*ea2,
                                    ei0[0]*ea0 + ei0[1]*ea1 + ei0[2]*ea2);
            sc[ni][1] += __fdividef(fi0[0]*eb0 + fi0[1]*eb1 + fi0[2]*eb2,
                                    ei0[0]*eb0 + ei0[1]*eb1 + ei0[2]*eb2);
            sc[ni][2] += __fdividef(fi1[0]*ea0 + fi1[1]*ea1 + fi1[2]*ea2,
                                    ei1[0]*ea0 + ei1[1]*ea1 + ei1[2]*ea2);
            sc[ni][3] += __fdividef(fi1[0]*eb0 + fi1[1]*eb1 + fi1[2]*eb2,
                                    ei1[0]*eb0 + ei1[1]*eb1 + ei1[2]*eb2);
        }

        // ---- warp-local online softmax ----
        float mx0 = -1e30f, mx1 = -1e30f;
#pragma unroll
        for (int ni = 0; ni < 8; ni++) {
            mx0 = fmaxf(mx0, fmaxf(sc[ni][0], sc[ni][1]));
            mx1 = fmaxf(mx1, fmaxf(sc[ni][2], sc[ni][3]));
        }
        mx0 = fmaxf(mx0, __shfl_xor_sync(0xffffffffu, mx0, 1));
        mx0 = fmaxf(mx0, __shfl_xor_sync(0xffffffffu, mx0, 2));
        mx1 = fmaxf(mx1, __shfl_xor_sync(0xffffffffu, mx1, 1));
        mx1 = fmaxf(mx1, __shfl_xor_sync(0xffffffffu, mx1, 2));
        float mn0 = fmaxf(m0, mx0);
        float mn1 = fmaxf(m1, mx1);
        float corr0 = __expf(m0 - mn0);
        float corr1 = __expf(m1 - mn1);

        float rs0 = 0.f, rs1 = 0.f;
        unsigned ph[8][2], pl[8][2];
#pragma unroll
        for (int ni = 0; ni < 8; ni++) {
            float p0 = __expf(sc[ni][0] - mn0);
            float p1 = __expf(sc[ni][1] - mn0);
            float p2 = __expf(sc[ni][2] - mn1);
            float p3 = __expf(sc[ni][3] - mn1);
            rs0 += p0 + p1;
            rs1 += p2 + p3;
            __nv_bfloat16 h0 = __float2bfloat16_rn(p0);
            __nv_bfloat16 h1 = __float2bfloat16_rn(p1);
            __nv_bfloat16 h2 = __float2bfloat16_rn(p2);
            __nv_bfloat16 h3 = __float2bfloat16_rn(p3);
            ph[ni][0] = pack_bf16(h0, h1);
            ph[ni][1] = pack_bf16(h2, h3);
            pl[ni][0] = pack_bf16(__float2bfloat16_rn(p0 - __bfloat162float(h0)),
                                  __float2bfloat16_rn(p1 - __bfloat162float(h1)));
            pl[ni][1] = pack_bf16(__float2bfloat16_rn(p2 - __bfloat162float(h2)),
                                  __float2bfloat16_rn(p3 - __bfloat162float(h3)));
        }
        rs0 += __shfl_xor_sync(0xffffffffu, rs0, 1);
        rs0 += __shfl_xor_sync(0xffffffffu, rs0, 2);
        rs1 += __shfl_xor_sync(0xffffffffu, rs1, 1);
        rs1 += __shfl_xor_sync(0xffffffffu, rs1, 2);
        l0 = l0*corr0 + rs0;
        l1 = l1*corr1 + rs1;
        m0 = mn0;
        m1 = mn1;

        // ---- O = O*corr + P V : V b-frags via ldmatrix.x4.trans ----
#pragma unroll
        for (int ni = 0; ni < 8; ni++) {
            acc[ni][0] *= corr0; acc[ni][1] *= corr0;
            acc[ni][2] *= corr1; acc[ni][3] *= corr1;
        }
#pragma unroll
        for (int ks = 0; ks < 4; ks++) {
            unsigned pah[4], pal[4];
            pah[0] = ph[2*ks  ][0];
            pah[1] = ph[2*ks  ][1];
            pah[2] = ph[2*ks+1][0];
            pah[3] = ph[2*ks+1][1];
            pal[0] = pl[2*ks  ][0];
            pal[1] = pl[2*ks  ][1];
            pal[2] = pl[2*ks+1][0];
            pal[3] = pl[2*ks+1][1];
#pragma unroll
            for (int np = 0; np < 4; np++) {
                unsigned vaddr = vrow_off + (unsigned)(ks*(16*BSTR*2) + np*32);
                unsigned t0, t1, t2, t3, u0, u1, u2, u3;
                LDMX4T(t0, t1, t2, t3, Vhb + vaddr);
                LDMX4T(u0, u1, u2, u3, Vlb + vaddr);
                unsigned vh0[2] = {t0, t1};
                unsigned vh1[2] = {t2, t3};
                unsigned vl0[2] = {u0, u1};
                unsigned vl1[2] = {u2, u3};
                MMA_BF16(acc[2*np    ], pah, vh0);
                MMA_BF16(acc[2*np    ], pal, vh0);
                MMA_BF16(acc[2*np    ], pah, vl0);
                MMA_BF16(acc[2*np + 1], pah, vh1);
                MMA_BF16(acc[2*np + 1], pal, vh1);
                MMA_BF16(acc[2*np + 1], pah, vl1);
            }
        }
        __syncthreads();
    }

    // ---- epilogue ----
    float inv0 = __frcp_rn(l0);
    float inv1 = __frcp_rn(l1);
    size_t gr0 = (size_t)(bb*SEQ + i0 + r0);
    size_t gr1 = (size_t)(bb*SEQ + i0 + r1);
#pragma unroll
    for (int ni = 0; ni < 8; ni++) {
        int col = hh*HD + ni*8 + tc;
        *(float2*)(g_ctx + gr0*DIM + col) =
            make_float2(acc[ni][0]*inv0, acc[ni][1]*inv0);
        *(float2*)(g_ctx + gr1*DIM + col) =
            make_float2(acc[ni][2]*inv1, acc[ni][3]*inv1);
    }
}

// ---------------- launcher ----------------
extern "C" void kernel_launch(void* const* d_in, const int* in_sizes, int n_in,
                              void* d_out, int out_size)
{
    (void)in_sizes; (void)n_in; (void)out_size;
    const float* x    = (const float*)d_in[0];
    const float* Wq   = (const float*)d_in[1];
    const float* bq   = (const float*)d_in[2];
    const float* Wk   = (const float*)d_in[3];
    const float* bk   = (const float*)d_in[4];
    const float* Wv   = (const float*)d_in[5];
    const float* bv   = (const float*)d_in[6];
    const float* Wo   = (const float*)d_in[7];
    const float* bo   = (const float*)d_in[8];
    const float* relW = (const float*)d_in[9];
    const float* relb = (const float*)d_in[10];
    const float* lb   = (const float*)d_in[11];
    const float* gW   = (const float*)d_in[12];
    const float* gb   = (const float*)d_in[13];

    __nv_bfloat16 *qh, *ql, *kh, *kl, *vh, *vl;
    float *ctx;
    cudaGetSymbolAddress((void**)&qh,  g_qh);
    cudaGetSymbolAddress((void**)&ql,  g_ql);
    cudaGetSymbolAddress((void**)&kh,  g_kh);
    cudaGetSymbolAddress((void**)&kl,  g_kl);
    cudaGetSymbolAddress((void**)&vh,  g_vh);
    cudaGetSymbolAddress((void**)&vl,  g_vl);
    cudaGetSymbolAddress((void**)&ctx, g_ctx);

    cudaFuncSetAttribute(sgemm_bf16x3,
                         cudaFuncAttributeMaxDynamicSharedMemorySize, GSM_BYTES);
    cudaFuncSetAttribute(sgemm_qkv_split,
                         cudaFuncAttributeMaxDynamicSharedMemorySize, GSM_BYTES);
    cudaFuncSetAttribute(attn_mma,
                         cudaFuncAttributeMaxDynamicSharedMemorySize, ATTN_SMEM);

    dim3 ggrid(DIM/128, MROWS/128);
    sgemm_qkv_split<<<ggrid, 256, GSM_BYTES>>>(x, Wq, bq, qh, ql, 0.125f, MROWS, DIM, DIM);
    sgemm_qkv_split<<<ggrid, 256, GSM_BYTES>>>(x, Wk, bk, kh, kl, 1.0f,   MROWS, DIM, DIM);
    sgemm_qkv_split<<<ggrid, 256, GSM_BYTES>>>(x, Wv, bv, vh, vl, 1.0f,   MROWS, DIM, DIM);
    proj_small<<<MROWS, 256>>>(x, relW, relb, gW, gb);

    attn_mma<<<dim3(SEQ/128, HEADS, BATCH), 256, ATTN_SMEM>>>(lb);

    sgemm_bf16x3<<<ggrid, 256, GSM_BYTES>>>(ctx, Wo, bo, (float*)d_out, MROWS, DIM, DIM);
}